// round 1
// baseline (speedup 1.0000x reference)
#include <cuda_runtime.h>
#include <cuda_bf16.h>
#include <cstdint>
#include <cstddef>

#define NN 100000
#define EE 800000
#define DD 128
#define NCLS 64

// ---------------------------------------------------------------------------
// Scratch (no runtime allocation allowed)
// ---------------------------------------------------------------------------
__device__ float g_m  [(size_t)NN * DD];
__device__ float g_agg[(size_t)NN * DD];
__device__ float g_h1 [(size_t)NN * DD];
__device__ float g_h2 [(size_t)NN * DD];

// ---------------------------------------------------------------------------
// Dual-source SGEMM:  C = relu(A1 @ W1 + A2 @ W2 + bias)
// A1:[N,K1] A2:[N,K2] (optional, K2=0 to skip), W:[K,M] row-major, C:[N,M]
// ---------------------------------------------------------------------------
template<int BM, int BN, int BK, int TM, int TN>
__global__ void __launch_bounds__((BM / TM) * (BN / TN))
sage_gemm(const float* __restrict__ A1, const float* __restrict__ W1, int K1,
          const float* __restrict__ A2, const float* __restrict__ W2, int K2,
          const float* __restrict__ bias, float* __restrict__ C,
          int N, int M)
{
    constexpr int THREADS = (BM / TM) * (BN / TN);
    __shared__ float As[BK][BM];   // transposed tile: As[k][m]
    __shared__ float Bs[BK][BN];

    const int brow = blockIdx.y * BM;
    const int tid  = threadIdx.x;
    const int tcol = tid % (BN / TN);
    const int trow = tid / (BN / TN);

    float acc[TM][TN];
    #pragma unroll
    for (int i = 0; i < TM; i++)
        #pragma unroll
        for (int j = 0; j < TN; j++) acc[i][j] = 0.0f;

    constexpr int A_F4  = BM * BK / 4;
    constexpr int A_PER = A_F4 / THREADS;
    constexpr int B_F4  = BK * BN / 4;
    constexpr int B_PER = B_F4 / THREADS;

    #pragma unroll 1
    for (int phase = 0; phase < 2; phase++) {
        const float* A = phase ? A2 : A1;
        const float* W = phase ? W2 : W1;
        const int    K = phase ? K2 : K1;
        if (K == 0) continue;

        #pragma unroll 1
        for (int k0 = 0; k0 < K; k0 += BK) {
            // --- load A tile (transposed into As) ---
            #pragma unroll
            for (int l = 0; l < A_PER; l++) {
                int idx = tid + l * THREADS;      // float4 index within tile
                int r   = idx / (BK / 4);         // row in tile
                int c4  = idx % (BK / 4);         // float4 col
                float4 v = make_float4(0.f, 0.f, 0.f, 0.f);
                int grow = brow + r;
                if (grow < N)
                    v = *reinterpret_cast<const float4*>(
                            &A[(size_t)grow * K + k0 + c4 * 4]);
                As[c4 * 4 + 0][r] = v.x;
                As[c4 * 4 + 1][r] = v.y;
                As[c4 * 4 + 2][r] = v.z;
                As[c4 * 4 + 3][r] = v.w;
            }
            // --- load W tile ---
            #pragma unroll
            for (int l = 0; l < B_PER; l++) {
                int idx = tid + l * THREADS;
                int r   = idx / (BN / 4);
                int c4  = idx % (BN / 4);
                float4 v = *reinterpret_cast<const float4*>(
                               &W[(size_t)(k0 + r) * M + c4 * 4]);
                *reinterpret_cast<float4*>(&Bs[r][c4 * 4]) = v;
            }
            __syncthreads();

            #pragma unroll
            for (int kk = 0; kk < BK; kk++) {
                float a[TM], b[TN];
                #pragma unroll
                for (int i = 0; i < TM; i++) a[i] = As[kk][trow * TM + i];
                #pragma unroll
                for (int j = 0; j < TN; j++) b[j] = Bs[kk][tcol * TN + j];
                #pragma unroll
                for (int i = 0; i < TM; i++)
                    #pragma unroll
                    for (int j = 0; j < TN; j++)
                        acc[i][j] = fmaf(a[i], b[j], acc[i][j]);
            }
            __syncthreads();
        }
    }

    // --- epilogue: bias + relu, vectorized store ---
    #pragma unroll
    for (int i = 0; i < TM; i++) {
        int grow = brow + trow * TM + i;
        if (grow >= N) continue;
        #pragma unroll
        for (int j = 0; j < TN; j += 4) {
            int gcol = tcol * TN + j;
            float4 v;
            v.x = fmaxf(acc[i][j + 0] + bias[gcol + 0], 0.0f);
            v.y = fmaxf(acc[i][j + 1] + bias[gcol + 1], 0.0f);
            v.z = fmaxf(acc[i][j + 2] + bias[gcol + 2], 0.0f);
            v.w = fmaxf(acc[i][j + 3] + bias[gcol + 3], 0.0f);
            *reinterpret_cast<float4*>(&C[(size_t)grow * M + gcol]) = v;
        }
    }
}

// fc_self has no bias in reference; fold by using a zero bias buffer? No —
// reference: h = x@Ws + agg@Wn + bn  (single bias bn). So dual-GEMM bias = bn. OK.

// ---------------------------------------------------------------------------
// Zero-fill
// ---------------------------------------------------------------------------
__global__ void zero_kernel(float* __restrict__ p, size_t n4)
{
    size_t i = (size_t)blockIdx.x * blockDim.x + threadIdx.x;
    size_t stride = (size_t)gridDim.x * blockDim.x;
    float4 z = make_float4(0.f, 0.f, 0.f, 0.f);
    for (; i < n4; i += stride)
        reinterpret_cast<float4*>(p)[i] = z;
}

// ---------------------------------------------------------------------------
// Scatter-max over edges: agg[dst] = max(agg[dst], m[src]) elementwise.
// m >= 0 (post-relu), agg zero-initialized => int-reinterpret atomicMax valid,
// and v == 0 contributes nothing (init already 0) => skip atomic.
// Block = 256 threads = 2 edges x 128 features.
// ---------------------------------------------------------------------------
__global__ void scatter_max_kernel(const float* __restrict__ m,
                                   const int* __restrict__ src,
                                   const int* __restrict__ dst,
                                   float* __restrict__ agg, int E)
{
    int e = blockIdx.x * 2 + (threadIdx.x >> 7);
    int t = threadIdx.x & 127;
    if (e >= E) return;
    int s = src[e];
    int d = dst[e];
    float v = m[(size_t)s * DD + t];
    if (v > 0.0f)
        atomicMax(reinterpret_cast<int*>(&agg[(size_t)d * DD + t]),
                  __float_as_int(v));
}

// ---------------------------------------------------------------------------
// Fused log-softmax over 64 classes: one warp per row, 2 values per lane.
// ---------------------------------------------------------------------------
__global__ void log_softmax_kernel(const float* __restrict__ h,
                                   float* __restrict__ out, int N)
{
    int row  = blockIdx.x * 8 + (threadIdx.x >> 5);
    int lane = threadIdx.x & 31;
    if (row >= N) return;
    const float* r = h + (size_t)row * NCLS;
    float v0 = r[lane];
    float v1 = r[lane + 32];
    float mx = fmaxf(v0, v1);
    #pragma unroll
    for (int o = 16; o; o >>= 1)
        mx = fmaxf(mx, __shfl_xor_sync(0xFFFFFFFFu, mx, o));
    float s = expf(v0 - mx) + expf(v1 - mx);
    #pragma unroll
    for (int o = 16; o; o >>= 1)
        s += __shfl_xor_sync(0xFFFFFFFFu, s, o);
    float lse = logf(s) + mx;
    out[(size_t)row * NCLS + lane]      = v0 - lse;
    out[(size_t)row * NCLS + lane + 32] = v1 - lse;
}

// ---------------------------------------------------------------------------
// Launch
// ---------------------------------------------------------------------------
extern "C" void kernel_launch(void* const* d_in, const int* in_sizes, int n_in,
                              void* d_out, int out_size)
{
    const float* x    = (const float*)d_in[0];
    const int*   esrc = (const int*)  d_in[1];
    const int*   edst = (const int*)  d_in[2];

    const float* Wp[3], *bp[3], *Ws[3], *Wn[3], *bn[3];
    for (int i = 0; i < 3; i++) {
        Wp[i] = (const float*)d_in[3 + 5 * i + 0];
        bp[i] = (const float*)d_in[3 + 5 * i + 1];
        Ws[i] = (const float*)d_in[3 + 5 * i + 2];
        Wn[i] = (const float*)d_in[3 + 5 * i + 3];
        bn[i] = (const float*)d_in[3 + 5 * i + 4];
    }

    float *m_p, *agg_p, *h1_p, *h2_p;
    cudaGetSymbolAddress((void**)&m_p,   g_m);
    cudaGetSymbolAddress((void**)&agg_p, g_agg);
    cudaGetSymbolAddress((void**)&h1_p,  g_h1);
    cudaGetSymbolAddress((void**)&h2_p,  g_h2);

    const int N = NN, E = EE;
    dim3 gemm_grid128(1, (N + 127) / 128);
    dim3 gemm_grid64(1, (N + 127) / 128);
    int  scatter_blocks = (E + 1) / 2;
    size_t agg_f4 = (size_t)N * DD / 4;

    const float* h = x;           // current layer input
    float* hbuf[2] = { h1_p, h2_p };

    for (int layer = 0; layer < 3; layer++) {
        // 1) m = relu(h @ Wp + bp)    [N,128]
        sage_gemm<128, 128, 16, 8, 8><<<gemm_grid128, 256>>>(
            h, Wp[layer], DD, nullptr, nullptr, 0, bp[layer], m_p, N, DD);

        // 2) agg = segment_max(m[src], dst)  (zero-init + atomicMax)
        zero_kernel<<<2048, 256>>>(agg_p, agg_f4);
        scatter_max_kernel<<<scatter_blocks, 256>>>(m_p, esrc, edst, agg_p, E);

        // 3) h' = relu(h @ Ws + agg @ Wn + bn)
        if (layer < 2) {
            float* out = hbuf[layer & 1];
            sage_gemm<128, 128, 16, 8, 8><<<gemm_grid128, 256>>>(
                h, Ws[layer], DD, agg_p, Wn[layer], DD, bn[layer], out, N, DD);
            h = out;
        } else {
            // final layer: M = 64 classes, result into g_m (reused)
            sage_gemm<128, 64, 16, 8, 8><<<gemm_grid64, 128>>>(
                h, Ws[layer], DD, agg_p, Wn[layer], DD, bn[layer], m_p, N, NCLS);
        }
    }

    // 4) log_softmax over 64 classes
    log_softmax_kernel<<<(N + 7) / 8, 256>>>(m_p, (float*)d_out, N);
}

// round 2
// speedup vs baseline: 1.1035x; 1.1035x over previous
#include <cuda_runtime.h>
#include <cuda_bf16.h>
#include <cstdint>
#include <cstddef>

#define NN 100000
#define EE 800000
#define DD 128
#define NCLS 64

// ---------------------------------------------------------------------------
// Scratch (no runtime allocation allowed)
// ---------------------------------------------------------------------------
__device__ float g_m  [(size_t)NN * DD];
__device__ float g_agg[(size_t)NN * DD];
__device__ float g_h1 [(size_t)NN * DD];
__device__ float g_h2 [(size_t)NN * DD];
// split+transposed weights: 9 weights (layer*3 + {Wp,Ws,Wn}), each up to 128x128
__device__ float g_whi[9][DD * DD];
__device__ float g_wlo[9][DD * DD];

// ---------------------------------------------------------------------------
// tf32 helpers
// ---------------------------------------------------------------------------
__device__ __forceinline__ float to_tf32(float x)
{
    uint32_t u;
    asm("cvt.rna.tf32.f32 %0, %1;" : "=r"(u) : "f"(x));
    return __uint_as_float(u);
}

__device__ __forceinline__ void mma8(float* c, const float* a, float b0, float b1)
{
    asm volatile(
        "mma.sync.aligned.m16n8k8.row.col.f32.tf32.tf32.f32 "
        "{%0,%1,%2,%3}, {%4,%5,%6,%7}, {%8,%9}, {%0,%1,%2,%3};\n"
        : "+f"(c[0]), "+f"(c[1]), "+f"(c[2]), "+f"(c[3])
        : "r"(__float_as_uint(a[0])), "r"(__float_as_uint(a[1])),
          "r"(__float_as_uint(a[2])), "r"(__float_as_uint(a[3])),
          "r"(__float_as_uint(b0)),  "r"(__float_as_uint(b1)));
}

// ---------------------------------------------------------------------------
// Weight prep: W[K,M] row-major -> Wt_hi[M][K], Wt_lo[M][K]  (3xTF32 split)
// ---------------------------------------------------------------------------
__global__ void split_transpose_w(const float* __restrict__ W,
                                  float* __restrict__ hi,
                                  float* __restrict__ lo, int K, int M)
{
    int idx = blockIdx.x * blockDim.x + threadIdx.x;
    if (idx >= K * M) return;
    int k = idx / M;
    int m = idx % M;
    float v  = W[idx];
    float vh = to_tf32(v);
    float vl = to_tf32(v - vh);
    hi[m * K + k] = vh;
    lo[m * K + k] = vl;
}

// ---------------------------------------------------------------------------
// Dual-source 3xTF32 tensor-core GEMM:
//   C = relu(A1 @ W1 + A2 @ W2 + bias)
// A:[N,K] row-major fp32; W given pre-transposed+split as Wt[M][K] hi/lo.
// Block tile 128 x BN, BK=32, 256 threads (8 warps: 4 along M, 2 along N).
// ---------------------------------------------------------------------------
template<int BN>
__global__ void __launch_bounds__(256)
sage_gemm_tf32(const float* __restrict__ A1,
               const float* __restrict__ B1h, const float* __restrict__ B1l, int K1,
               const float* __restrict__ A2,
               const float* __restrict__ B2h, const float* __restrict__ B2l, int K2,
               const float* __restrict__ bias, float* __restrict__ C,
               int N, int M)
{
    constexpr int BM = 128;
    constexpr int BK = 32;
    constexpr int STR = BK + 4;         // 36-float row stride: conflict-free frag reads
    constexpr int WN = BN / 2;          // warp n-extent
    constexpr int NT = BN / 16;         // 8x8-n mma tiles per warp (8 or 4)

    extern __shared__ float smem[];
    float* As_hi = smem;
    float* As_lo = As_hi + BM * STR;
    float* Bs_hi = As_lo + BM * STR;
    float* Bs_lo = Bs_hi + BN * STR;

    const int tid  = threadIdx.x;
    const int lane = tid & 31;
    const int warp = tid >> 5;
    const int wm   = warp & 3;          // 0..3
    const int wn   = warp >> 2;         // 0..1
    const int g    = lane >> 2;         // 0..7
    const int t    = lane & 3;          // 0..3
    const int brow = blockIdx.y * BM;

    float c[2][NT][4];
    #pragma unroll
    for (int mt = 0; mt < 2; mt++)
        #pragma unroll
        for (int nt = 0; nt < NT; nt++)
            #pragma unroll
            for (int i = 0; i < 4; i++) c[mt][nt][i] = 0.0f;

    #pragma unroll 1
    for (int phase = 0; phase < 2; phase++) {
        const float* A  = phase ? A2  : A1;
        const float* Bh = phase ? B2h : B1h;
        const float* Bl = phase ? B2l : B1l;
        const int    K  = phase ? K2  : K1;
        if (K == 0) continue;

        #pragma unroll 1
        for (int k0 = 0; k0 < K; k0 += BK) {
            // ---- load + split A tile [BM x BK] ----
            #pragma unroll
            for (int l = 0; l < (BM * BK / 4) / 256; l++) {
                int idx = tid + l * 256;        // float4 index
                int r   = idx >> 3;             // row (BK/4 = 8 f4 per row)
                int c4  = idx & 7;
                int grow = brow + r;
                float4 v = make_float4(0.f, 0.f, 0.f, 0.f);
                if (grow < N)
                    v = *reinterpret_cast<const float4*>(
                            &A[(size_t)grow * K + k0 + c4 * 4]);
                float4 h4, l4;
                h4.x = to_tf32(v.x); l4.x = to_tf32(v.x - h4.x);
                h4.y = to_tf32(v.y); l4.y = to_tf32(v.y - h4.y);
                h4.z = to_tf32(v.z); l4.z = to_tf32(v.z - h4.z);
                h4.w = to_tf32(v.w); l4.w = to_tf32(v.w - h4.w);
                // (r*STR + c4*4)*4 bytes = 144r + 16c4 -> 16B aligned
                *reinterpret_cast<float4*>(&As_hi[r * STR + c4 * 4]) = h4;
                *reinterpret_cast<float4*>(&As_lo[r * STR + c4 * 4]) = l4;
            }
            // ---- load B tiles (already split, row n-major, stride K) ----
            #pragma unroll
            for (int l = 0; l < (BN * BK / 4) / 256; l++) {
                int idx = tid + l * 256;
                int n   = idx >> 3;
                int c4  = idx & 7;
                float4 vh = *reinterpret_cast<const float4*>(
                                &Bh[(size_t)n * K + k0 + c4 * 4]);
                float4 vl = *reinterpret_cast<const float4*>(
                                &Bl[(size_t)n * K + k0 + c4 * 4]);
                *reinterpret_cast<float4*>(&Bs_hi[n * STR + c4 * 4]) = vh;
                *reinterpret_cast<float4*>(&Bs_lo[n * STR + c4 * 4]) = vl;
            }
            __syncthreads();

            // ---- mma over 4 k-steps of 8 ----
            #pragma unroll
            for (int ks = 0; ks < BK / 8; ks++) {
                int kk = ks * 8;
                float ah[2][4], al[2][4];
                #pragma unroll
                for (int mt = 0; mt < 2; mt++) {
                    int r0 = wm * 32 + mt * 16 + g;
                    ah[mt][0] = As_hi[r0 * STR + kk + t];
                    ah[mt][1] = As_hi[(r0 + 8) * STR + kk + t];
                    ah[mt][2] = As_hi[r0 * STR + kk + t + 4];
                    ah[mt][3] = As_hi[(r0 + 8) * STR + kk + t + 4];
                    al[mt][0] = As_lo[r0 * STR + kk + t];
                    al[mt][1] = As_lo[(r0 + 8) * STR + kk + t];
                    al[mt][2] = As_lo[r0 * STR + kk + t + 4];
                    al[mt][3] = As_lo[(r0 + 8) * STR + kk + t + 4];
                }
                #pragma unroll
                for (int nt = 0; nt < NT; nt++) {
                    int nc = wn * WN + nt * 8 + g;
                    float bh0 = Bs_hi[nc * STR + kk + t];
                    float bh1 = Bs_hi[nc * STR + kk + t + 4];
                    float bl0 = Bs_lo[nc * STR + kk + t];
                    float bl1 = Bs_lo[nc * STR + kk + t + 4];
                    #pragma unroll
                    for (int mt = 0; mt < 2; mt++) {
                        mma8(c[mt][nt], ah[mt], bh0, bh1);   // hi*hi
                        mma8(c[mt][nt], ah[mt], bl0, bl1);   // hi*lo
                        mma8(c[mt][nt], al[mt], bh0, bh1);   // lo*hi
                    }
                }
            }
            __syncthreads();
        }
    }

    // ---- epilogue: bias + relu ----
    #pragma unroll
    for (int mt = 0; mt < 2; mt++) {
        int row = brow + wm * 32 + mt * 16 + g;
        #pragma unroll
        for (int nt = 0; nt < NT; nt++) {
            int col = wn * WN + nt * 8 + 2 * t;
            float b0 = bias[col], b1 = bias[col + 1];
            if (row < N) {
                float2 v;
                v.x = fmaxf(c[mt][nt][0] + b0, 0.0f);
                v.y = fmaxf(c[mt][nt][1] + b1, 0.0f);
                *reinterpret_cast<float2*>(&C[(size_t)row * M + col]) = v;
            }
            if (row + 8 < N) {
                float2 v;
                v.x = fmaxf(c[mt][nt][2] + b0, 0.0f);
                v.y = fmaxf(c[mt][nt][3] + b1, 0.0f);
                *reinterpret_cast<float2*>(&C[(size_t)(row + 8) * M + col]) = v;
            }
        }
    }
}

// ---------------------------------------------------------------------------
// Zero-fill
// ---------------------------------------------------------------------------
__global__ void zero_kernel(float* __restrict__ p, size_t n4)
{
    size_t i = (size_t)blockIdx.x * blockDim.x + threadIdx.x;
    size_t stride = (size_t)gridDim.x * blockDim.x;
    float4 z = make_float4(0.f, 0.f, 0.f, 0.f);
    for (; i < n4; i += stride)
        reinterpret_cast<float4*>(p)[i] = z;
}

// ---------------------------------------------------------------------------
// Scatter-max over edges (messages >= 0, agg zero-init -> int atomicMax valid)
// ---------------------------------------------------------------------------
__global__ void scatter_max_kernel(const float* __restrict__ m,
                                   const int* __restrict__ src,
                                   const int* __restrict__ dst,
                                   float* __restrict__ agg, int E)
{
    int e = blockIdx.x * 2 + (threadIdx.x >> 7);
    int t = threadIdx.x & 127;
    if (e >= E) return;
    int s = src[e];
    int d = dst[e];
    float v = m[(size_t)s * DD + t];
    if (v > 0.0f)
        atomicMax(reinterpret_cast<int*>(&agg[(size_t)d * DD + t]),
                  __float_as_int(v));
}

// ---------------------------------------------------------------------------
// log-softmax over 64 classes: one warp per row
// ---------------------------------------------------------------------------
__global__ void log_softmax_kernel(const float* __restrict__ h,
                                   float* __restrict__ out, int N)
{
    int row  = blockIdx.x * 8 + (threadIdx.x >> 5);
    int lane = threadIdx.x & 31;
    if (row >= N) return;
    const float* r = h + (size_t)row * NCLS;
    float v0 = r[lane];
    float v1 = r[lane + 32];
    float mx = fmaxf(v0, v1);
    #pragma unroll
    for (int o = 16; o; o >>= 1)
        mx = fmaxf(mx, __shfl_xor_sync(0xFFFFFFFFu, mx, o));
    float s = expf(v0 - mx) + expf(v1 - mx);
    #pragma unroll
    for (int o = 16; o; o >>= 1)
        s += __shfl_xor_sync(0xFFFFFFFFu, s, o);
    float lse = logf(s) + mx;
    out[(size_t)row * NCLS + lane]      = v0 - lse;
    out[(size_t)row * NCLS + lane + 32] = v1 - lse;
}

// ---------------------------------------------------------------------------
// Launch
// ---------------------------------------------------------------------------
extern "C" void kernel_launch(void* const* d_in, const int* in_sizes, int n_in,
                              void* d_out, int out_size)
{
    const float* x    = (const float*)d_in[0];
    const int*   esrc = (const int*)  d_in[1];
    const int*   edst = (const int*)  d_in[2];

    const float* Wp[3], *bp[3], *Ws[3], *Wn[3], *bn[3];
    for (int i = 0; i < 3; i++) {
        Wp[i] = (const float*)d_in[3 + 5 * i + 0];
        bp[i] = (const float*)d_in[3 + 5 * i + 1];
        Ws[i] = (const float*)d_in[3 + 5 * i + 2];
        Wn[i] = (const float*)d_in[3 + 5 * i + 3];
        bn[i] = (const float*)d_in[3 + 5 * i + 4];
    }
    int Mout[3] = { DD, DD, NCLS };

    float *m_p, *agg_p, *h1_p, *h2_p;
    cudaGetSymbolAddress((void**)&m_p,   g_m);
    cudaGetSymbolAddress((void**)&agg_p, g_agg);
    cudaGetSymbolAddress((void**)&h1_p,  g_h1);
    cudaGetSymbolAddress((void**)&h2_p,  g_h2);
    float *whi_p, *wlo_p;
    cudaGetSymbolAddress((void**)&whi_p, g_whi);
    cudaGetSymbolAddress((void**)&wlo_p, g_wlo);

    const int N = NN, E = EE;

    // dynamic smem sizes + opt-in (idempotent; immediate host-side call)
    const int STR = 36;
    size_t smem128 = (size_t)(128 * STR * 2 + 128 * STR * 2) * 4;
    size_t smem64  = (size_t)(128 * STR * 2 +  64 * STR * 2) * 4;
    cudaFuncSetAttribute(sage_gemm_tf32<128>,
                         cudaFuncAttributeMaxDynamicSharedMemorySize, (int)smem128);
    cudaFuncSetAttribute(sage_gemm_tf32<64>,
                         cudaFuncAttributeMaxDynamicSharedMemorySize, (int)smem64);

    // ---- prep: transpose + tf32-split all 9 weights ----
    const float* wsrc[9] = { Wp[0], Ws[0], Wn[0],
                             Wp[1], Ws[1], Wn[1],
                             Wp[2], Ws[2], Wn[2] };
    int wM[9] = { DD, DD, DD, DD, DD, DD, DD, NCLS, NCLS };
    for (int w = 0; w < 9; w++) {
        int total = DD * wM[w];
        split_transpose_w<<<(total + 255) / 256, 256>>>(
            wsrc[w], whi_p + w * DD * DD, wlo_p + w * DD * DD, DD, wM[w]);
    }

    dim3 ggrid(1, (N + 127) / 128);
    int scatter_blocks = (E + 1) / 2;
    size_t agg_f4 = (size_t)N * DD / 4;

    const float* h = x;
    float* hbuf[2] = { h1_p, h2_p };

    for (int layer = 0; layer < 3; layer++) {
        const float* wp_h = whi_p + (layer * 3 + 0) * DD * DD;
        const float* wp_l = wlo_p + (layer * 3 + 0) * DD * DD;
        const float* ws_h = whi_p + (layer * 3 + 1) * DD * DD;
        const float* ws_l = wlo_p + (layer * 3 + 1) * DD * DD;
        const float* wn_h = whi_p + (layer * 3 + 2) * DD * DD;
        const float* wn_l = wlo_p + (layer * 3 + 2) * DD * DD;

        // 1) m = relu(h @ Wp + bp)   [N,128]
        sage_gemm_tf32<128><<<ggrid, 256, smem128>>>(
            h, wp_h, wp_l, DD, nullptr, nullptr, nullptr, 0,
            bp[layer], m_p, N, DD);

        // 2) agg = segment_max(m[src], dst)
        zero_kernel<<<2048, 256>>>(agg_p, agg_f4);
        scatter_max_kernel<<<scatter_blocks, 256>>>(m_p, esrc, edst, agg_p, E);

        // 3) h' = relu(h @ Ws + agg @ Wn + bn)
        if (layer < 2) {
            float* out = hbuf[layer & 1];
            sage_gemm_tf32<128><<<ggrid, 256, smem128>>>(
                h, ws_h, ws_l, DD, agg_p, wn_h, wn_l, DD,
                bn[layer], out, N, DD);
            h = out;
        } else {
            sage_gemm_tf32<64><<<ggrid, 256, smem64>>>(
                h, ws_h, ws_l, DD, agg_p, wn_h, wn_l, DD,
                bn[layer], m_p, N, NCLS);
        }
    }

    log_softmax_kernel<<<(N + 7) / 8, 256>>>(m_p, (float*)d_out, N);
}

// round 3
// speedup vs baseline: 3.0727x; 2.7844x over previous
#include <cuda_runtime.h>
#include <cuda_bf16.h>
#include <cstdint>
#include <cstddef>

#define NN 100000
#define EE 800000
#define DD 128
#define NCLS 64

// ---------------------------------------------------------------------------
// Scratch (no runtime allocation allowed)
// ---------------------------------------------------------------------------
__device__ float g_m  [(size_t)NN * DD];
__device__ float g_agg[(size_t)NN * DD];
__device__ float g_h1 [(size_t)NN * DD];
__device__ float g_h2 [(size_t)NN * DD];
// bf16-split transposed weights: 9 slots (layer*3 + {Wp,Ws,Wn}), [M][K] layout
__device__ __nv_bfloat16 g_wh[9][DD * DD];
__device__ __nv_bfloat16 g_wl[9][DD * DD];
// CSR for dst-grouped edges
__device__ int g_deg[NN];
__device__ int g_off[NN];
__device__ int g_cur[NN];
__device__ int g_csr[EE];
__device__ int g_part[128];          // block partial sums for scan (98 used)

// ---------------------------------------------------------------------------
// Weight prep: all 9 weights in one launch.
// W[k][m] row-major -> hi/lo bf16 [m][K] (K = DD always).
// ---------------------------------------------------------------------------
struct WPrep { const float* src[9]; int M[9]; };

__global__ void prep_weights(WPrep p, __nv_bfloat16* __restrict__ hi,
                             __nv_bfloat16* __restrict__ lo)
{
    int w = blockIdx.y;
    int M = p.M[w];
    int idx = blockIdx.x * blockDim.x + threadIdx.x;
    if (idx >= DD * M) return;
    int k = idx / M;
    int m = idx % M;
    float v = p.src[w][idx];
    __nv_bfloat16 h = __float2bfloat16(v);
    float r = v - __bfloat162float(h);
    hi[(size_t)w * DD * DD + m * DD + k] = h;
    lo[(size_t)w * DD * DD + m * DD + k] = __float2bfloat16(r);
}

// ---------------------------------------------------------------------------
// CSR build: zero -> count -> scan(3 kernels) -> fill
// ---------------------------------------------------------------------------
__global__ void zero_deg_kernel()
{
    int i = blockIdx.x * blockDim.x + threadIdx.x;
    if (i < NN) g_deg[i] = 0;
}

__global__ void count_kernel(const int* __restrict__ dst)
{
    int e = blockIdx.x * blockDim.x + threadIdx.x;
    if (e < EE) atomicAdd(&g_deg[dst[e]], 1);
}

// block of 256 threads covers 1024 elements; writes block total
__global__ void scan1_kernel()
{
    __shared__ int sh[256];
    int tid = threadIdx.x;
    int base = blockIdx.x * 1024 + tid * 4;
    int s = 0;
    #pragma unroll
    for (int j = 0; j < 4; j++) {
        int idx = base + j;
        if (idx < NN) s += g_deg[idx];
    }
    sh[tid] = s;
    __syncthreads();
    for (int o = 128; o; o >>= 1) {
        if (tid < o) sh[tid] += sh[tid + o];
        __syncthreads();
    }
    if (tid == 0) g_part[blockIdx.x] = sh[0];
}

__global__ void scan2_kernel(int nblk)
{
    // single thread: exclusive scan of block partials (<= 98 elements)
    int run = 0;
    for (int i = 0; i < nblk; i++) {
        int v = g_part[i];
        g_part[i] = run;
        run += v;
    }
}

__global__ void scan3_kernel()
{
    __shared__ int sh[256];
    int tid = threadIdx.x;
    int base = blockIdx.x * 1024 + tid * 4;
    int v[4];
    int s = 0;
    #pragma unroll
    for (int j = 0; j < 4; j++) {
        int idx = base + j;
        v[j] = (idx < NN) ? g_deg[idx] : 0;
        s += v[j];
    }
    sh[tid] = s;
    __syncthreads();
    // Hillis-Steele inclusive scan over 256 thread sums
    #pragma unroll
    for (int o = 1; o < 256; o <<= 1) {
        int x = (tid >= o) ? sh[tid - o] : 0;
        __syncthreads();
        sh[tid] += x;
        __syncthreads();
    }
    int run = sh[tid] - s + g_part[blockIdx.x];   // exclusive prefix
    #pragma unroll
    for (int j = 0; j < 4; j++) {
        int idx = base + j;
        if (idx < NN) { g_off[idx] = run; g_cur[idx] = run; }
        run += v[j];
    }
}

__global__ void fill_kernel(const int* __restrict__ src,
                            const int* __restrict__ dst)
{
    int e = blockIdx.x * blockDim.x + threadIdx.x;
    if (e < EE) {
        int p = atomicAdd(&g_cur[dst[e]], 1);
        g_csr[p] = src[e];
    }
}

// ---------------------------------------------------------------------------
// Aggregation: warp per node, gather-max over in-edges (no atomics).
// Messages are >= 0 (post-relu), empty segment -> 0 (matches reference fixup).
// ---------------------------------------------------------------------------
__global__ void aggregate_kernel(const float* __restrict__ m,
                                 float* __restrict__ agg, int N)
{
    int node = blockIdx.x * 8 + (threadIdx.x >> 5);
    int lane = threadIdx.x & 31;
    if (node >= N) return;
    int o = g_off[node];
    int d = g_deg[node];
    float4 acc = make_float4(0.f, 0.f, 0.f, 0.f);
    for (int i = 0; i < d; i++) {
        int s = g_csr[o + i];   // uniform across warp
        float4 v = *reinterpret_cast<const float4*>(&m[(size_t)s * DD + lane * 4]);
        acc.x = fmaxf(acc.x, v.x);
        acc.y = fmaxf(acc.y, v.y);
        acc.z = fmaxf(acc.z, v.z);
        acc.w = fmaxf(acc.w, v.w);
    }
    *reinterpret_cast<float4*>(&agg[(size_t)node * DD + lane * 4]) = acc;
}

// ---------------------------------------------------------------------------
// bf16 split mma helper: m16n8k16, fp32 accumulate
// ---------------------------------------------------------------------------
__device__ __forceinline__ void mma16(float* c, const uint32_t* a,
                                      uint32_t b0, uint32_t b1)
{
    asm volatile(
        "mma.sync.aligned.m16n8k16.row.col.f32.bf16.bf16.f32 "
        "{%0,%1,%2,%3}, {%4,%5,%6,%7}, {%8,%9}, {%0,%1,%2,%3};\n"
        : "+f"(c[0]), "+f"(c[1]), "+f"(c[2]), "+f"(c[3])
        : "r"(a[0]), "r"(a[1]), "r"(a[2]), "r"(a[3]),
          "r"(b0), "r"(b1));
}

__device__ __forceinline__ uint32_t pack_bf16x2(float a, float b)
{
    __nv_bfloat162 h = __floats2bfloat162_rn(a, b);
    return *reinterpret_cast<uint32_t*>(&h);
}

// ---------------------------------------------------------------------------
// Dual-source bf16-split tensor-core GEMM:
//   C = relu(A1 @ W1 + A2 @ W2 + bias)
// A:[N,K] fp32 row-major (split on the fly); W pre-split bf16 [M][K].
// Block 128 x BN, BK=32, 256 threads (warps: 4 on M x 2 on N).
// Smem stores bf16 pairs (u32), row stride 20 u32 (16 data + 4 pad,
// conflict-free: banks 20g+t all distinct for g<8,t<4).
// ---------------------------------------------------------------------------
template<int BN>
__global__ void __launch_bounds__(256)
sage_gemm_bf16(const float* __restrict__ A1,
               const __nv_bfloat16* __restrict__ B1h,
               const __nv_bfloat16* __restrict__ B1l, int K1,
               const float* __restrict__ A2,
               const __nv_bfloat16* __restrict__ B2h,
               const __nv_bfloat16* __restrict__ B2l, int K2,
               const float* __restrict__ bias, float* __restrict__ C,
               int N, int M)
{
    constexpr int BM  = 128;
    constexpr int BK  = 32;        // k elements per tile
    constexpr int STRP = 20;       // u32 pairs per row (16 + 4 pad)
    constexpr int WN  = BN / 2;
    constexpr int NT  = BN / 16;   // 8-wide n tiles per warp

    __shared__ uint32_t As_hi[BM * STRP];
    __shared__ uint32_t As_lo[BM * STRP];
    __shared__ uint32_t Bs_hi[BN * STRP];
    __shared__ uint32_t Bs_lo[BN * STRP];

    const int tid  = threadIdx.x;
    const int lane = tid & 31;
    const int warp = tid >> 5;
    const int wm   = warp & 3;
    const int wn   = warp >> 2;
    const int g    = lane >> 2;
    const int t    = lane & 3;
    const int brow = blockIdx.y * BM;

    float c[2][NT][4];
    #pragma unroll
    for (int mt = 0; mt < 2; mt++)
        #pragma unroll
        for (int nt = 0; nt < NT; nt++)
            #pragma unroll
            for (int i = 0; i < 4; i++) c[mt][nt][i] = 0.0f;

    #pragma unroll 1
    for (int phase = 0; phase < 2; phase++) {
        const float* A = phase ? A2 : A1;
        const __nv_bfloat16* Bh = phase ? B2h : B1h;
        const __nv_bfloat16* Bl = phase ? B2l : B1l;
        const int K = phase ? K2 : K1;
        if (K == 0) continue;

        #pragma unroll 1
        for (int k0 = 0; k0 < K; k0 += BK) {
            // ---- A tile: load fp32, split to bf16 hi/lo pairs ----
            #pragma unroll
            for (int l = 0; l < 4; l++) {           // 1024 float4 / 256
                int idx = tid + l * 256;
                int r   = idx >> 3;                 // 8 float4 per row
                int c4  = idx & 7;
                int grow = brow + r;
                float4 v = make_float4(0.f, 0.f, 0.f, 0.f);
                if (grow < N)
                    v = *reinterpret_cast<const float4*>(
                            &A[(size_t)grow * K + k0 + c4 * 4]);
                float hx = __bfloat162float(__float2bfloat16(v.x));
                float hy = __bfloat162float(__float2bfloat16(v.y));
                float hz = __bfloat162float(__float2bfloat16(v.z));
                float hw = __bfloat162float(__float2bfloat16(v.w));
                uint32_t* ph = &As_hi[r * STRP + c4 * 2];
                uint32_t* pl = &As_lo[r * STRP + c4 * 2];
                ph[0] = pack_bf16x2(hx, hy);
                ph[1] = pack_bf16x2(hz, hw);
                pl[0] = pack_bf16x2(v.x - hx, v.y - hy);
                pl[1] = pack_bf16x2(v.z - hz, v.w - hw);
            }
            // ---- B tiles: pre-split bf16, copy 8 elements (uint4) at a time ----
            #pragma unroll
            for (int l = 0; l < (BN * 4) / 256; l++) {
                int idx = tid + l * 256;
                int n   = idx >> 2;                 // 4 uint4 per row
                int q   = idx & 3;
                uint4 vh = *reinterpret_cast<const uint4*>(
                               &Bh[(size_t)n * K + k0 + q * 8]);
                uint4 vl = *reinterpret_cast<const uint4*>(
                               &Bl[(size_t)n * K + k0 + q * 8]);
                *reinterpret_cast<uint4*>(&Bs_hi[n * STRP + q * 4]) = vh;
                *reinterpret_cast<uint4*>(&Bs_lo[n * STRP + q * 4]) = vl;
            }
            __syncthreads();

            // ---- 2 k-steps of 16 ----
            #pragma unroll
            for (int ks = 0; ks < 2; ks++) {
                int kp = ks * 8;
                uint32_t ah[2][4], al[2][4];
                #pragma unroll
                for (int mt = 0; mt < 2; mt++) {
                    int r0 = wm * 32 + mt * 16 + g;
                    ah[mt][0] = As_hi[r0 * STRP + kp + t];
                    ah[mt][1] = As_hi[(r0 + 8) * STRP + kp + t];
                    ah[mt][2] = As_hi[r0 * STRP + kp + t + 4];
                    ah[mt][3] = As_hi[(r0 + 8) * STRP + kp + t + 4];
                    al[mt][0] = As_lo[r0 * STRP + kp + t];
                    al[mt][1] = As_lo[(r0 + 8) * STRP + kp + t];
                    al[mt][2] = As_lo[r0 * STRP + kp + t + 4];
                    al[mt][3] = As_lo[(r0 + 8) * STRP + kp + t + 4];
                }
                #pragma unroll
                for (int nt = 0; nt < NT; nt++) {
                    int nc = wn * WN + nt * 8 + g;
                    uint32_t bh0 = Bs_hi[nc * STRP + kp + t];
                    uint32_t bh1 = Bs_hi[nc * STRP + kp + t + 4];
                    uint32_t bl0 = Bs_lo[nc * STRP + kp + t];
                    uint32_t bl1 = Bs_lo[nc * STRP + kp + t + 4];
                    #pragma unroll
                    for (int mt = 0; mt < 2; mt++) {
                        mma16(c[mt][nt], ah[mt], bh0, bh1);   // hi*hi
                        mma16(c[mt][nt], ah[mt], bl0, bl1);   // hi*lo
                        mma16(c[mt][nt], al[mt], bh0, bh1);   // lo*hi
                    }
                }
            }
            __syncthreads();
        }
    }

    // ---- epilogue: bias + relu ----
    #pragma unroll
    for (int mt = 0; mt < 2; mt++) {
        int row = brow + wm * 32 + mt * 16 + g;
        #pragma unroll
        for (int nt = 0; nt < NT; nt++) {
            int col = wn * WN + nt * 8 + 2 * t;
            float b0 = bias[col], b1 = bias[col + 1];
            if (row < N) {
                float2 v;
                v.x = fmaxf(c[mt][nt][0] + b0, 0.0f);
                v.y = fmaxf(c[mt][nt][1] + b1, 0.0f);
                *reinterpret_cast<float2*>(&C[(size_t)row * M + col]) = v;
            }
            if (row + 8 < N) {
                float2 v;
                v.x = fmaxf(c[mt][nt][2] + b0, 0.0f);
                v.y = fmaxf(c[mt][nt][3] + b1, 0.0f);
                *reinterpret_cast<float2*>(&C[(size_t)(row + 8) * M + col]) = v;
            }
        }
    }
}

// ---------------------------------------------------------------------------
// log-softmax over 64 classes: one warp per row
// ---------------------------------------------------------------------------
__global__ void log_softmax_kernel(const float* __restrict__ h,
                                   float* __restrict__ out, int N)
{
    int row  = blockIdx.x * 8 + (threadIdx.x >> 5);
    int lane = threadIdx.x & 31;
    if (row >= N) return;
    const float* r = h + (size_t)row * NCLS;
    float v0 = r[lane];
    float v1 = r[lane + 32];
    float mx = fmaxf(v0, v1);
    #pragma unroll
    for (int o = 16; o; o >>= 1)
        mx = fmaxf(mx, __shfl_xor_sync(0xFFFFFFFFu, mx, o));
    float s = expf(v0 - mx) + expf(v1 - mx);
    #pragma unroll
    for (int o = 16; o; o >>= 1)
        s += __shfl_xor_sync(0xFFFFFFFFu, s, o);
    float lse = logf(s) + mx;
    out[(size_t)row * NCLS + lane]      = v0 - lse;
    out[(size_t)row * NCLS + lane + 32] = v1 - lse;
}

// ---------------------------------------------------------------------------
// Launch
// ---------------------------------------------------------------------------
extern "C" void kernel_launch(void* const* d_in, const int* in_sizes, int n_in,
                              void* d_out, int out_size)
{
    const float* x    = (const float*)d_in[0];
    const int*   esrc = (const int*)  d_in[1];
    const int*   edst = (const int*)  d_in[2];

    const float* Wp[3], *bp[3], *Ws[3], *Wn[3], *bn[3];
    for (int i = 0; i < 3; i++) {
        Wp[i] = (const float*)d_in[3 + 5 * i + 0];
        bp[i] = (const float*)d_in[3 + 5 * i + 1];
        Ws[i] = (const float*)d_in[3 + 5 * i + 2];
        Wn[i] = (const float*)d_in[3 + 5 * i + 3];
        bn[i] = (const float*)d_in[3 + 5 * i + 4];
    }

    float *m_p, *agg_p, *h1_p, *h2_p;
    cudaGetSymbolAddress((void**)&m_p,   g_m);
    cudaGetSymbolAddress((void**)&agg_p, g_agg);
    cudaGetSymbolAddress((void**)&h1_p,  g_h1);
    cudaGetSymbolAddress((void**)&h2_p,  g_h2);
    __nv_bfloat16 *wh_p, *wl_p;
    cudaGetSymbolAddress((void**)&wh_p, g_wh);
    cudaGetSymbolAddress((void**)&wl_p, g_wl);

    const int N = NN, E = EE;

    // ---- weight prep: one launch for all 9 ----
    WPrep wp;
    const float* wsrc[9] = { Wp[0], Ws[0], Wn[0],
                             Wp[1], Ws[1], Wn[1],
                             Wp[2], Ws[2], Wn[2] };
    int wM[9] = { DD, DD, DD, DD, DD, DD, DD, NCLS, NCLS };
    for (int i = 0; i < 9; i++) { wp.src[i] = wsrc[i]; wp.M[i] = wM[i]; }
    prep_weights<<<dim3((DD * DD + 255) / 256, 9), 256>>>(wp, wh_p, wl_p);

    // ---- CSR build (dst-grouped) ----
    const int SCAN_BLKS = (NN + 1023) / 1024;    // 98
    zero_deg_kernel<<<(NN + 255) / 256, 256>>>();
    count_kernel<<<(E + 255) / 256, 256>>>(edst);
    scan1_kernel<<<SCAN_BLKS, 256>>>();
    scan2_kernel<<<1, 1>>>(SCAN_BLKS);
    scan3_kernel<<<SCAN_BLKS, 256>>>();
    fill_kernel<<<(E + 255) / 256, 256>>>(esrc, edst);

    dim3 ggrid(1, (N + 127) / 128);
    const float* h = x;
    float* hbuf[2] = { h1_p, h2_p };

    for (int layer = 0; layer < 3; layer++) {
        const __nv_bfloat16* wph = wh_p + (layer * 3 + 0) * DD * DD;
        const __nv_bfloat16* wpl = wl_p + (layer * 3 + 0) * DD * DD;
        const __nv_bfloat16* wsh = wh_p + (layer * 3 + 1) * DD * DD;
        const __nv_bfloat16* wsl = wl_p + (layer * 3 + 1) * DD * DD;
        const __nv_bfloat16* wnh = wh_p + (layer * 3 + 2) * DD * DD;
        const __nv_bfloat16* wnl = wl_p + (layer * 3 + 2) * DD * DD;

        // 1) m = relu(h @ Wp + bp)
        sage_gemm_bf16<128><<<ggrid, 256>>>(
            h, wph, wpl, DD, nullptr, nullptr, nullptr, 0,
            bp[layer], m_p, N, DD);

        // 2) agg = segment_max(m[src], dst) via CSR gather-max
        aggregate_kernel<<<(N + 7) / 8, 256>>>(m_p, agg_p, N);

        // 3) h' = relu(h @ Ws + agg @ Wn + bn)
        if (layer < 2) {
            float* out = hbuf[layer & 1];
            sage_gemm_bf16<128><<<ggrid, 256>>>(
                h, wsh, wsl, DD, agg_p, wnh, wnl, DD,
                bn[layer], out, N, DD);
            h = out;
        } else {
            sage_gemm_bf16<64><<<ggrid, 256>>>(
                h, wsh, wsl, DD, agg_p, wnh, wnl, DD,
                bn[layer], m_p, N, NCLS);
        }
    }

    log_softmax_kernel<<<(N + 7) / 8, 256>>>(m_p, (float*)d_out, N);
}

// round 4
// speedup vs baseline: 3.3358x; 1.0856x over previous
#include <cuda_runtime.h>
#include <cuda_bf16.h>
#include <cstdint>
#include <cstddef>

#define NN 100000
#define EE 800000
#define DD 128
#define NCLS 64

// ---------------------------------------------------------------------------
// Scratch (no runtime allocation allowed)
// ---------------------------------------------------------------------------
__device__ float g_m  [(size_t)NN * DD];
__device__ float g_agg[(size_t)NN * DD];
__device__ float g_h1 [(size_t)NN * DD];
__device__ float g_h2 [(size_t)NN * DD];
// bf16-split transposed weights: 9 slots (layer*3 + {Wp,Ws,Wn}), [M][K] layout
__device__ __nv_bfloat16 g_wh[9][DD * DD];
__device__ __nv_bfloat16 g_wl[9][DD * DD];
// CSR for dst-grouped edges
__device__ int g_deg[NN];
__device__ int g_off[NN];
__device__ int g_cur[NN];
__device__ int g_csr[EE];
__device__ int g_part[128];

// ---------------------------------------------------------------------------
// Weight prep: all 9 weights in one launch.
// W[k][m] row-major -> hi/lo bf16 [m][K] (K = DD always).
// ---------------------------------------------------------------------------
struct WPrep { const float* src[9]; int M[9]; };

__global__ void prep_weights(WPrep p, __nv_bfloat16* __restrict__ hi,
                             __nv_bfloat16* __restrict__ lo)
{
    int w = blockIdx.y;
    int M = p.M[w];
    int idx = blockIdx.x * blockDim.x + threadIdx.x;
    if (idx >= DD * M) return;
    int k = idx / M;
    int m = idx % M;
    float v = p.src[w][idx];
    __nv_bfloat16 h = __float2bfloat16(v);
    float r = v - __bfloat162float(h);
    hi[(size_t)w * DD * DD + m * DD + k] = h;
    lo[(size_t)w * DD * DD + m * DD + k] = __float2bfloat16(r);
}

// ---------------------------------------------------------------------------
// CSR build: zero -> count -> scan(3 kernels) -> fill
// ---------------------------------------------------------------------------
__global__ void zero_deg_kernel()
{
    int i = blockIdx.x * blockDim.x + threadIdx.x;
    if (i < NN) g_deg[i] = 0;
}

__global__ void count_kernel(const int* __restrict__ dst)
{
    int e = blockIdx.x * blockDim.x + threadIdx.x;
    if (e < EE) atomicAdd(&g_deg[dst[e]], 1);
}

__global__ void scan1_kernel()
{
    __shared__ int sh[256];
    int tid = threadIdx.x;
    int base = blockIdx.x * 1024 + tid * 4;
    int s = 0;
    #pragma unroll
    for (int j = 0; j < 4; j++) {
        int idx = base + j;
        if (idx < NN) s += g_deg[idx];
    }
    sh[tid] = s;
    __syncthreads();
    for (int o = 128; o; o >>= 1) {
        if (tid < o) sh[tid] += sh[tid + o];
        __syncthreads();
    }
    if (tid == 0) g_part[blockIdx.x] = sh[0];
}

__global__ void scan2_kernel(int nblk)
{
    int run = 0;
    for (int i = 0; i < nblk; i++) {
        int v = g_part[i];
        g_part[i] = run;
        run += v;
    }
}

__global__ void scan3_kernel()
{
    __shared__ int sh[256];
    int tid = threadIdx.x;
    int base = blockIdx.x * 1024 + tid * 4;
    int v[4];
    int s = 0;
    #pragma unroll
    for (int j = 0; j < 4; j++) {
        int idx = base + j;
        v[j] = (idx < NN) ? g_deg[idx] : 0;
        s += v[j];
    }
    sh[tid] = s;
    __syncthreads();
    #pragma unroll
    for (int o = 1; o < 256; o <<= 1) {
        int x = (tid >= o) ? sh[tid - o] : 0;
        __syncthreads();
        sh[tid] += x;
        __syncthreads();
    }
    int run = sh[tid] - s + g_part[blockIdx.x];
    #pragma unroll
    for (int j = 0; j < 4; j++) {
        int idx = base + j;
        if (idx < NN) { g_off[idx] = run; g_cur[idx] = run; }
        run += v[j];
    }
}

__global__ void fill_kernel(const int* __restrict__ src,
                            const int* __restrict__ dst)
{
    int e = blockIdx.x * blockDim.x + threadIdx.x;
    if (e < EE) {
        int p = atomicAdd(&g_cur[dst[e]], 1);
        g_csr[p] = src[e];
    }
}

// ---------------------------------------------------------------------------
// Aggregation: warp per node, gather-max over in-edges (no atomics),
// unrolled x4 for memory-level parallelism.
// ---------------------------------------------------------------------------
__global__ void aggregate_kernel(const float* __restrict__ m,
                                 float* __restrict__ agg, int N)
{
    int node = blockIdx.x * 8 + (threadIdx.x >> 5);
    int lane = threadIdx.x & 31;
    if (node >= N) return;
    int o = g_off[node];
    int d = g_deg[node];
    float4 acc = make_float4(0.f, 0.f, 0.f, 0.f);
    int i = 0;
    for (; i + 4 <= d; i += 4) {
        int s0 = g_csr[o + i + 0];
        int s1 = g_csr[o + i + 1];
        int s2 = g_csr[o + i + 2];
        int s3 = g_csr[o + i + 3];
        float4 v0 = *reinterpret_cast<const float4*>(&m[(size_t)s0 * DD + lane * 4]);
        float4 v1 = *reinterpret_cast<const float4*>(&m[(size_t)s1 * DD + lane * 4]);
        float4 v2 = *reinterpret_cast<const float4*>(&m[(size_t)s2 * DD + lane * 4]);
        float4 v3 = *reinterpret_cast<const float4*>(&m[(size_t)s3 * DD + lane * 4]);
        acc.x = fmaxf(fmaxf(acc.x, fmaxf(v0.x, v1.x)), fmaxf(v2.x, v3.x));
        acc.y = fmaxf(fmaxf(acc.y, fmaxf(v0.y, v1.y)), fmaxf(v2.y, v3.y));
        acc.z = fmaxf(fmaxf(acc.z, fmaxf(v0.z, v1.z)), fmaxf(v2.z, v3.z));
        acc.w = fmaxf(fmaxf(acc.w, fmaxf(v0.w, v1.w)), fmaxf(v2.w, v3.w));
    }
    for (; i < d; i++) {
        int s = g_csr[o + i];
        float4 v = *reinterpret_cast<const float4*>(&m[(size_t)s * DD + lane * 4]);
        acc.x = fmaxf(acc.x, v.x);
        acc.y = fmaxf(acc.y, v.y);
        acc.z = fmaxf(acc.z, v.z);
        acc.w = fmaxf(acc.w, v.w);
    }
    *reinterpret_cast<float4*>(&agg[(size_t)node * DD + lane * 4]) = acc;
}

// ---------------------------------------------------------------------------
// mma / ldmatrix helpers
// ---------------------------------------------------------------------------
__device__ __forceinline__ void mma16(float* c, const uint32_t* a,
                                      uint32_t b0, uint32_t b1)
{
    asm volatile(
        "mma.sync.aligned.m16n8k16.row.col.f32.bf16.bf16.f32 "
        "{%0,%1,%2,%3}, {%4,%5,%6,%7}, {%8,%9}, {%0,%1,%2,%3};\n"
        : "+f"(c[0]), "+f"(c[1]), "+f"(c[2]), "+f"(c[3])
        : "r"(a[0]), "r"(a[1]), "r"(a[2]), "r"(a[3]),
          "r"(b0), "r"(b1));
}

__device__ __forceinline__ void ldmx4(uint32_t* r, uint32_t addr)
{
    asm volatile(
        "ldmatrix.sync.aligned.m8n8.x4.shared.b16 {%0,%1,%2,%3}, [%4];"
        : "=r"(r[0]), "=r"(r[1]), "=r"(r[2]), "=r"(r[3]) : "r"(addr));
}

__device__ __forceinline__ uint32_t pack_bf16x2(float a, float b)
{
    __nv_bfloat162 h = __floats2bfloat162_rn(a, b);
    return *reinterpret_cast<uint32_t*>(&h);
}

// ---------------------------------------------------------------------------
// Dual-source bf16-split tensor-core GEMM (ldmatrix fragment loads):
//   C = relu(A1 @ W1 + A2 @ W2 + bias)
// A:[N,K] fp32 row-major (split on the fly); W pre-split bf16 [M][K].
// Block 128 x BN, BK=64, 256 threads (warps: 4 on M x 2 on N).
// Smem rows: 32 data u32 (64 bf16) + 4 pad = stride 36 u32 (conflict-free
// for both ldmatrix phases and fragment column reads).
// ---------------------------------------------------------------------------
template<int BN>
__global__ void __launch_bounds__(256)
sage_gemm_bf16(const float* __restrict__ A1,
               const __nv_bfloat16* __restrict__ B1h,
               const __nv_bfloat16* __restrict__ B1l, int K1,
               const float* __restrict__ A2,
               const __nv_bfloat16* __restrict__ B2h,
               const __nv_bfloat16* __restrict__ B2l, int K2,
               const float* __restrict__ bias, float* __restrict__ C,
               int N, int M)
{
    constexpr int BM   = 128;
    constexpr int BK   = 64;         // k elements per tile
    constexpr int STRP = 36;         // u32 per row (32 data + 4 pad)
    constexpr int WN   = BN / 2;     // warp n extent
    constexpr int NT   = BN / 16;    // n8 tiles per warp
    constexpr int NP   = NT / 2;     // n16 ldmatrix pairs per warp

    extern __shared__ uint32_t smem_u[];
    uint32_t* As_hi = smem_u;
    uint32_t* As_lo = As_hi + BM * STRP;
    uint32_t* Bs_hi = As_lo + BM * STRP;
    uint32_t* Bs_lo = Bs_hi + BN * STRP;

    const int tid  = threadIdx.x;
    const int lane = tid & 31;
    const int warp = tid >> 5;
    const int wm   = warp & 3;
    const int wn   = warp >> 2;
    const int t    = lane & 3;
    const int brow = blockIdx.y * BM;

    const uint32_t as_hi_b = (uint32_t)__cvta_generic_to_shared(As_hi);
    const uint32_t as_lo_b = (uint32_t)__cvta_generic_to_shared(As_lo);
    const uint32_t bs_hi_b = (uint32_t)__cvta_generic_to_shared(Bs_hi);
    const uint32_t bs_lo_b = (uint32_t)__cvta_generic_to_shared(Bs_lo);

    // ldmatrix lane->address row mapping (u32 index offsets, x4 = 4 bytes each)
    // A: lanes 0-15 -> m rows 0..15 (k lo half), 16-31 -> same rows (k hi half)
    const uint32_t a_row_off = (uint32_t)(lane & 15) * STRP + (uint32_t)(lane >> 4) * 4;
    // B: lanes {0-7,8-15,16-23,24-31} -> (n0..7,klo),(n0..7,khi),(n8..15,klo),(n8..15,khi)
    const uint32_t b_row_off = ((uint32_t)(lane & 7) + (uint32_t)(lane >> 4) * 8) * STRP
                             + (uint32_t)((lane >> 3) & 1) * 4;

    float c[2][NT][4];
    #pragma unroll
    for (int mt = 0; mt < 2; mt++)
        #pragma unroll
        for (int nt = 0; nt < NT; nt++)
            #pragma unroll
            for (int i = 0; i < 4; i++) c[mt][nt][i] = 0.0f;

    #pragma unroll 1
    for (int phase = 0; phase < 2; phase++) {
        const float* A = phase ? A2 : A1;
        const __nv_bfloat16* Bh = phase ? B2h : B1h;
        const __nv_bfloat16* Bl = phase ? B2l : B1l;
        const int K = phase ? K2 : K1;
        if (K == 0) continue;

        #pragma unroll 1
        for (int k0 = 0; k0 < K; k0 += BK) {
            // ---- A tile [BM x BK] fp32 -> split bf16 hi/lo ----
            #pragma unroll
            for (int l = 0; l < (BM * BK / 4) / 256; l++) {   // 8 iters
                int idx = tid + l * 256;
                int r   = idx >> 4;              // 16 float4 per row
                int c4  = idx & 15;
                int grow = brow + r;
                float4 v = make_float4(0.f, 0.f, 0.f, 0.f);
                if (grow < N)
                    v = *reinterpret_cast<const float4*>(
                            &A[(size_t)grow * K + k0 + c4 * 4]);
                float hx = __bfloat162float(__float2bfloat16(v.x));
                float hy = __bfloat162float(__float2bfloat16(v.y));
                float hz = __bfloat162float(__float2bfloat16(v.z));
                float hw = __bfloat162float(__float2bfloat16(v.w));
                uint32_t* ph = &As_hi[r * STRP + c4 * 2];
                uint32_t* pl = &As_lo[r * STRP + c4 * 2];
                ph[0] = pack_bf16x2(hx, hy);
                ph[1] = pack_bf16x2(hz, hw);
                pl[0] = pack_bf16x2(v.x - hx, v.y - hy);
                pl[1] = pack_bf16x2(v.z - hz, v.w - hw);
            }
            // ---- B tiles: pre-split bf16, 16B copies ----
            #pragma unroll
            for (int l = 0; l < (BN * 8) / 256; l++) {
                int idx = tid + l * 256;
                int n   = idx >> 3;              // 8 uint4 per row
                int q   = idx & 7;
                uint4 vh = *reinterpret_cast<const uint4*>(
                               &Bh[(size_t)n * K + k0 + q * 8]);
                uint4 vl = *reinterpret_cast<const uint4*>(
                               &Bl[(size_t)n * K + k0 + q * 8]);
                *reinterpret_cast<uint4*>(&Bs_hi[n * STRP + q * 4]) = vh;
                *reinterpret_cast<uint4*>(&Bs_lo[n * STRP + q * 4]) = vl;
            }
            __syncthreads();

            // ---- 4 k-steps of 16 ----
            #pragma unroll
            for (int ks = 0; ks < BK / 16; ks++) {
                int kp = ks * 8;                 // u32 offset within row
                uint32_t ah[2][4], al[2][4];
                #pragma unroll
                for (int mt = 0; mt < 2; mt++) {
                    uint32_t off = ((uint32_t)(wm * 32 + mt * 16) * STRP
                                    + (uint32_t)kp + a_row_off) * 4u;
                    ldmx4(ah[mt], as_hi_b + off);
                    ldmx4(al[mt], as_lo_b + off);
                }
                #pragma unroll
                for (int p = 0; p < NP; p++) {
                    uint32_t off = ((uint32_t)(wn * WN + p * 16) * STRP
                                    + (uint32_t)kp + b_row_off) * 4u;
                    uint32_t bh[4], bl[4];
                    ldmx4(bh, bs_hi_b + off);
                    ldmx4(bl, bs_lo_b + off);
                    #pragma unroll
                    for (int sub = 0; sub < 2; sub++) {
                        int nt = p * 2 + sub;
                        #pragma unroll
                        for (int mt = 0; mt < 2; mt++) {
                            mma16(c[mt][nt], ah[mt], bh[2*sub], bh[2*sub+1]); // hi*hi
                            mma16(c[mt][nt], ah[mt], bl[2*sub], bl[2*sub+1]); // hi*lo
                            mma16(c[mt][nt], al[mt], bh[2*sub], bh[2*sub+1]); // lo*hi
                        }
                    }
                }
            }
            __syncthreads();
        }
    }

    // ---- epilogue: bias + relu ----
    const int g = lane >> 2;
    #pragma unroll
    for (int mt = 0; mt < 2; mt++) {
        int row = brow + wm * 32 + mt * 16 + g;
        #pragma unroll
        for (int nt = 0; nt < NT; nt++) {
            int col = wn * WN + nt * 8 + 2 * t;
            float b0 = bias[col], b1 = bias[col + 1];
            if (row < N) {
                float2 v;
                v.x = fmaxf(c[mt][nt][0] + b0, 0.0f);
                v.y = fmaxf(c[mt][nt][1] + b1, 0.0f);
                *reinterpret_cast<float2*>(&C[(size_t)row * M + col]) = v;
            }
            if (row + 8 < N) {
                float2 v;
                v.x = fmaxf(c[mt][nt][2] + b0, 0.0f);
                v.y = fmaxf(c[mt][nt][3] + b1, 0.0f);
                *reinterpret_cast<float2*>(&C[(size_t)(row + 8) * M + col]) = v;
            }
        }
    }
}

// ---------------------------------------------------------------------------
// log-softmax over 64 classes: one warp per row
// ---------------------------------------------------------------------------
__global__ void log_softmax_kernel(const float* __restrict__ h,
                                   float* __restrict__ out, int N)
{
    int row  = blockIdx.x * 8 + (threadIdx.x >> 5);
    int lane = threadIdx.x & 31;
    if (row >= N) return;
    const float* r = h + (size_t)row * NCLS;
    float v0 = r[lane];
    float v1 = r[lane + 32];
    float mx = fmaxf(v0, v1);
    #pragma unroll
    for (int o = 16; o; o >>= 1)
        mx = fmaxf(mx, __shfl_xor_sync(0xFFFFFFFFu, mx, o));
    float s = expf(v0 - mx) + expf(v1 - mx);
    #pragma unroll
    for (int o = 16; o; o >>= 1)
        s += __shfl_xor_sync(0xFFFFFFFFu, s, o);
    float lse = logf(s) + mx;
    out[(size_t)row * NCLS + lane]      = v0 - lse;
    out[(size_t)row * NCLS + lane + 32] = v1 - lse;
}

// ---------------------------------------------------------------------------
// Launch
// ---------------------------------------------------------------------------
extern "C" void kernel_launch(void* const* d_in, const int* in_sizes, int n_in,
                              void* d_out, int out_size)
{
    const float* x    = (const float*)d_in[0];
    const int*   esrc = (const int*)  d_in[1];
    const int*   edst = (const int*)  d_in[2];

    const float* Wp[3], *bp[3], *Ws[3], *Wn[3], *bn[3];
    for (int i = 0; i < 3; i++) {
        Wp[i] = (const float*)d_in[3 + 5 * i + 0];
        bp[i] = (const float*)d_in[3 + 5 * i + 1];
        Ws[i] = (const float*)d_in[3 + 5 * i + 2];
        Wn[i] = (const float*)d_in[3 + 5 * i + 3];
        bn[i] = (const float*)d_in[3 + 5 * i + 4];
    }

    float *m_p, *agg_p, *h1_p, *h2_p;
    cudaGetSymbolAddress((void**)&m_p,   g_m);
    cudaGetSymbolAddress((void**)&agg_p, g_agg);
    cudaGetSymbolAddress((void**)&h1_p,  g_h1);
    cudaGetSymbolAddress((void**)&h2_p,  g_h2);
    __nv_bfloat16 *wh_p, *wl_p;
    cudaGetSymbolAddress((void**)&wh_p, g_wh);
    cudaGetSymbolAddress((void**)&wl_p, g_wl);

    const int N = NN, E = EE;

    // dynamic smem: (2*BM + 2*BN) * 36 u32
    size_t smem128 = (size_t)(2 * 128 + 2 * 128) * 36 * 4;   // 73728
    size_t smem64  = (size_t)(2 * 128 + 2 * 64)  * 36 * 4;   // 55296
    cudaFuncSetAttribute(sage_gemm_bf16<128>,
                         cudaFuncAttributeMaxDynamicSharedMemorySize, (int)smem128);
    cudaFuncSetAttribute(sage_gemm_bf16<64>,
                         cudaFuncAttributeMaxDynamicSharedMemorySize, (int)smem64);

    // ---- weight prep ----
    WPrep wp;
    const float* wsrc[9] = { Wp[0], Ws[0], Wn[0],
                             Wp[1], Ws[1], Wn[1],
                             Wp[2], Ws[2], Wn[2] };
    int wM[9] = { DD, DD, DD, DD, DD, DD, DD, NCLS, NCLS };
    for (int i = 0; i < 9; i++) { wp.src[i] = wsrc[i]; wp.M[i] = wM[i]; }
    prep_weights<<<dim3((DD * DD + 255) / 256, 9), 256>>>(wp, wh_p, wl_p);

    // ---- CSR build ----
    const int SCAN_BLKS = (NN + 1023) / 1024;    // 98
    zero_deg_kernel<<<(NN + 255) / 256, 256>>>();
    count_kernel<<<(E + 255) / 256, 256>>>(edst);
    scan1_kernel<<<SCAN_BLKS, 256>>>();
    scan2_kernel<<<1, 1>>>(SCAN_BLKS);
    scan3_kernel<<<SCAN_BLKS, 256>>>();
    fill_kernel<<<(E + 255) / 256, 256>>>(esrc, edst);

    dim3 ggrid(1, (N + 127) / 128);
    const float* h = x;
    float* hbuf[2] = { h1_p, h2_p };

    for (int layer = 0; layer < 3; layer++) {
        const __nv_bfloat16* wph = wh_p + (layer * 3 + 0) * DD * DD;
        const __nv_bfloat16* wpl = wl_p + (layer * 3 + 0) * DD * DD;
        const __nv_bfloat16* wsh = wh_p + (layer * 3 + 1) * DD * DD;
        const __nv_bfloat16* wsl = wl_p + (layer * 3 + 1) * DD * DD;
        const __nv_bfloat16* wnh = wh_p + (layer * 3 + 2) * DD * DD;
        const __nv_bfloat16* wnl = wl_p + (layer * 3 + 2) * DD * DD;

        // 1) m = relu(h @ Wp + bp)
        sage_gemm_bf16<128><<<ggrid, 256, smem128>>>(
            h, wph, wpl, DD, nullptr, nullptr, nullptr, 0,
            bp[layer], m_p, N, DD);

        // 2) agg = segment_max(m[src], dst) via CSR gather-max
        aggregate_kernel<<<(N + 7) / 8, 256>>>(m_p, agg_p, N);

        // 3) h' = relu(h @ Ws + agg @ Wn + bn)
        if (layer < 2) {
            float* out = hbuf[layer & 1];
            sage_gemm_bf16<128><<<ggrid, 256, smem128>>>(
                h, wsh, wsl, DD, agg_p, wnh, wnl, DD,
                bn[layer], out, N, DD);
            h = out;
        } else {
            sage_gemm_bf16<64><<<ggrid, 256, smem64>>>(
                h, wsh, wsl, DD, agg_p, wnh, wnl, DD,
                bn[layer], m_p, N, NCLS);
        }
    }

    log_softmax_kernel<<<(N + 7) / 8, 256>>>(m_p, (float*)d_out, N);
}

// round 5
// speedup vs baseline: 3.9067x; 1.1712x over previous
#include <cuda_runtime.h>
#include <cuda_bf16.h>
#include <cstdint>
#include <cstddef>

#define NN 100000
#define EE 800000
#define DD 128
#define NCLS 64

// ---------------------------------------------------------------------------
// Scratch (no runtime allocation allowed)
// ---------------------------------------------------------------------------
__device__ float g_m  [(size_t)NN * DD];
__device__ float g_agg[(size_t)NN * DD];
__device__ float g_h1 [(size_t)NN * DD];
__device__ float g_h2 [(size_t)NN * DD];
__device__ __nv_bfloat16 g_wh[9][DD * DD];
__device__ __nv_bfloat16 g_wl[9][DD * DD];
__device__ int g_deg[NN];
__device__ int g_off[NN];
__device__ int g_cur[NN];
__device__ int g_csr[EE];
__device__ int g_part[128];

// ---------------------------------------------------------------------------
// Weight prep
// ---------------------------------------------------------------------------
struct WPrep { const float* src[9]; int M[9]; };

__global__ void prep_weights(WPrep p, __nv_bfloat16* __restrict__ hi,
                             __nv_bfloat16* __restrict__ lo)
{
    int w = blockIdx.y;
    int M = p.M[w];
    int idx = blockIdx.x * blockDim.x + threadIdx.x;
    if (idx >= DD * M) return;
    int k = idx / M;
    int m = idx % M;
    float v = p.src[w][idx];
    __nv_bfloat16 h = __float2bfloat16(v);
    float r = v - __bfloat162float(h);
    hi[(size_t)w * DD * DD + m * DD + k] = h;
    lo[(size_t)w * DD * DD + m * DD + k] = __float2bfloat16(r);
}

// ---------------------------------------------------------------------------
// CSR build
// ---------------------------------------------------------------------------
__global__ void zero_deg_kernel()
{
    int i = blockIdx.x * blockDim.x + threadIdx.x;
    if (i < NN) g_deg[i] = 0;
}

__global__ void count_kernel(const int* __restrict__ dst)
{
    int e = blockIdx.x * blockDim.x + threadIdx.x;
    if (e < EE) atomicAdd(&g_deg[dst[e]], 1);
}

__global__ void scan1_kernel()
{
    __shared__ int sh[256];
    int tid = threadIdx.x;
    int base = blockIdx.x * 1024 + tid * 4;
    int s = 0;
    #pragma unroll
    for (int j = 0; j < 4; j++) {
        int idx = base + j;
        if (idx < NN) s += g_deg[idx];
    }
    sh[tid] = s;
    __syncthreads();
    for (int o = 128; o; o >>= 1) {
        if (tid < o) sh[tid] += sh[tid + o];
        __syncthreads();
    }
    if (tid == 0) g_part[blockIdx.x] = sh[0];
}

__global__ void scan2_kernel(int nblk)
{
    int run = 0;
    for (int i = 0; i < nblk; i++) {
        int v = g_part[i];
        g_part[i] = run;
        run += v;
    }
}

__global__ void scan3_kernel()
{
    __shared__ int sh[256];
    int tid = threadIdx.x;
    int base = blockIdx.x * 1024 + tid * 4;
    int v[4];
    int s = 0;
    #pragma unroll
    for (int j = 0; j < 4; j++) {
        int idx = base + j;
        v[j] = (idx < NN) ? g_deg[idx] : 0;
        s += v[j];
    }
    sh[tid] = s;
    __syncthreads();
    #pragma unroll
    for (int o = 1; o < 256; o <<= 1) {
        int x = (tid >= o) ? sh[tid - o] : 0;
        __syncthreads();
        sh[tid] += x;
        __syncthreads();
    }
    int run = sh[tid] - s + g_part[blockIdx.x];
    #pragma unroll
    for (int j = 0; j < 4; j++) {
        int idx = base + j;
        if (idx < NN) { g_off[idx] = run; g_cur[idx] = run; }
        run += v[j];
    }
}

__global__ void fill_kernel(const int* __restrict__ src,
                            const int* __restrict__ dst)
{
    int e = blockIdx.x * blockDim.x + threadIdx.x;
    if (e < EE) {
        int p = atomicAdd(&g_cur[dst[e]], 1);
        g_csr[p] = src[e];
    }
}

// ---------------------------------------------------------------------------
// Aggregation: warp per node, gather-max (no atomics), unrolled x4
// ---------------------------------------------------------------------------
__global__ void aggregate_kernel(const float* __restrict__ m,
                                 float* __restrict__ agg, int N)
{
    int node = blockIdx.x * 8 + (threadIdx.x >> 5);
    int lane = threadIdx.x & 31;
    if (node >= N) return;
    int o = g_off[node];
    int d = g_deg[node];
    float4 acc = make_float4(0.f, 0.f, 0.f, 0.f);
    int i = 0;
    for (; i + 4 <= d; i += 4) {
        int s0 = g_csr[o + i + 0];
        int s1 = g_csr[o + i + 1];
        int s2 = g_csr[o + i + 2];
        int s3 = g_csr[o + i + 3];
        float4 v0 = *reinterpret_cast<const float4*>(&m[(size_t)s0 * DD + lane * 4]);
        float4 v1 = *reinterpret_cast<const float4*>(&m[(size_t)s1 * DD + lane * 4]);
        float4 v2 = *reinterpret_cast<const float4*>(&m[(size_t)s2 * DD + lane * 4]);
        float4 v3 = *reinterpret_cast<const float4*>(&m[(size_t)s3 * DD + lane * 4]);
        acc.x = fmaxf(fmaxf(acc.x, fmaxf(v0.x, v1.x)), fmaxf(v2.x, v3.x));
        acc.y = fmaxf(fmaxf(acc.y, fmaxf(v0.y, v1.y)), fmaxf(v2.y, v3.y));
        acc.z = fmaxf(fmaxf(acc.z, fmaxf(v0.z, v1.z)), fmaxf(v2.z, v3.z));
        acc.w = fmaxf(fmaxf(acc.w, fmaxf(v0.w, v1.w)), fmaxf(v2.w, v3.w));
    }
    for (; i < d; i++) {
        int s = g_csr[o + i];
        float4 v = *reinterpret_cast<const float4*>(&m[(size_t)s * DD + lane * 4]);
        acc.x = fmaxf(acc.x, v.x);
        acc.y = fmaxf(acc.y, v.y);
        acc.z = fmaxf(acc.z, v.z);
        acc.w = fmaxf(acc.w, v.w);
    }
    *reinterpret_cast<float4*>(&agg[(size_t)node * DD + lane * 4]) = acc;
}

// ---------------------------------------------------------------------------
// mma / ldmatrix / cp.async helpers
// ---------------------------------------------------------------------------
__device__ __forceinline__ void mma16(float* c, const uint32_t* a,
                                      uint32_t b0, uint32_t b1)
{
    asm volatile(
        "mma.sync.aligned.m16n8k16.row.col.f32.bf16.bf16.f32 "
        "{%0,%1,%2,%3}, {%4,%5,%6,%7}, {%8,%9}, {%0,%1,%2,%3};\n"
        : "+f"(c[0]), "+f"(c[1]), "+f"(c[2]), "+f"(c[3])
        : "r"(a[0]), "r"(a[1]), "r"(a[2]), "r"(a[3]),
          "r"(b0), "r"(b1));
}

__device__ __forceinline__ void ldmx4(uint32_t* r, uint32_t addr)
{
    asm volatile(
        "ldmatrix.sync.aligned.m8n8.x4.shared.b16 {%0,%1,%2,%3}, [%4];"
        : "=r"(r[0]), "=r"(r[1]), "=r"(r[2]), "=r"(r[3]) : "r"(addr));
}

__device__ __forceinline__ void cp16(uint32_t saddr, const void* gaddr)
{
    asm volatile("cp.async.cg.shared.global [%0], [%1], 16;\n"
                 :: "r"(saddr), "l"(gaddr));
}

__device__ __forceinline__ void cp_commit()
{
    asm volatile("cp.async.commit_group;\n");
}

__device__ __forceinline__ void cp_wait0()
{
    asm volatile("cp.async.wait_group 0;\n");
}

__device__ __forceinline__ uint32_t pack_bf16x2(float a, float b)
{
    __nv_bfloat162 h = __floats2bfloat162_rn(a, b);
    return *reinterpret_cast<uint32_t*>(&h);
}

// ---------------------------------------------------------------------------
// Dual-source bf16-split tensor-core GEMM, software-pipelined:
//   C = relu(A1 @ W1 [+ A2 @ W2] + bias),  K = 128 fixed.
// k-tiles of 64 (2 per phase). B double-buffered via cp.async; A fp32
// register-staged during MMAs, converted to smem after the tile sync.
// Smem: A(hi/lo) 36 KB single + B(hi/lo) 2x36 KB -> 108 KB, 2 CTAs/SM.
// ---------------------------------------------------------------------------
template<int BN>
__global__ void __launch_bounds__(256, 2)
sage_gemm_bf16(const float* __restrict__ A1,
               const __nv_bfloat16* __restrict__ B1h,
               const __nv_bfloat16* __restrict__ B1l,
               const float* __restrict__ A2,
               const __nv_bfloat16* __restrict__ B2h,
               const __nv_bfloat16* __restrict__ B2l,
               const float* __restrict__ bias, float* __restrict__ C,
               int N, int M)
{
    constexpr int BM   = 128;
    constexpr int BK   = 64;
    constexpr int STRP = 36;          // u32 per row (32 data + 4 pad)
    constexpr int WN   = BN / 2;
    constexpr int NT   = BN / 16;
    constexpr int NP   = NT / 2;
    constexpr int BBUF = BN * STRP;   // u32 per B buffer (one of hi/lo)

    extern __shared__ __align__(16) uint32_t smem_u[];
    uint32_t* As_hi = smem_u;                      // BM*STRP
    uint32_t* As_lo = As_hi + BM * STRP;
    uint32_t* Bs    = As_lo + BM * STRP;           // [2 bufs][hi|lo]

    const int tid  = threadIdx.x;
    const int lane = tid & 31;
    const int warp = tid >> 5;
    const int wm   = warp & 3;
    const int wn   = warp >> 2;
    const int t4   = lane & 3;
    const int brow = blockIdx.y * BM;

    const uint32_t as_hi_b = (uint32_t)__cvta_generic_to_shared(As_hi);
    const uint32_t as_lo_b = (uint32_t)__cvta_generic_to_shared(As_lo);
    const uint32_t bs_b    = (uint32_t)__cvta_generic_to_shared(Bs);

    const uint32_t a_row_off = (uint32_t)(lane & 15) * STRP + (uint32_t)(lane >> 4) * 4;
    const uint32_t b_row_off = ((uint32_t)(lane & 7) + (uint32_t)(lane >> 4) * 8) * STRP
                             + (uint32_t)((lane >> 3) & 1) * 4;

    const float* Ab[2]            = { A1, A2 ? A2 : A1 };
    const __nv_bfloat16* Bhb[2]   = { B1h, B2h ? B2h : B1h };
    const __nv_bfloat16* Blb[2]   = { B1l, B2l ? B2l : B1l };
    const int T = A2 ? 4 : 2;

    float c[2][NT][4];
    #pragma unroll
    for (int mt = 0; mt < 2; mt++)
        #pragma unroll
        for (int nt = 0; nt < NT; nt++)
            #pragma unroll
            for (int i = 0; i < 4; i++) c[mt][nt][i] = 0.0f;

    float4 areg[8];

    // ---- helpers as macros over locals ----
    #define LOAD_A_REG(t_) do {                                               \
        const float* A_ = Ab[(t_) >> 1];                                      \
        int koff_ = ((t_) & 1) * BK;                                          \
        _Pragma("unroll")                                                     \
        for (int l = 0; l < 8; l++) {                                         \
            int idx = tid + l * 256;                                          \
            int r   = idx >> 4;                                               \
            int c4  = idx & 15;                                               \
            int grow = brow + r;                                              \
            areg[l] = (grow < N)                                              \
                ? *reinterpret_cast<const float4*>(                           \
                      &A_[(size_t)grow * DD + koff_ + c4 * 4])                \
                : make_float4(0.f, 0.f, 0.f, 0.f);                            \
        }                                                                     \
    } while (0)

    #define STORE_A_SMEM() do {                                               \
        _Pragma("unroll")                                                     \
        for (int l = 0; l < 8; l++) {                                         \
            int idx = tid + l * 256;                                          \
            int r   = idx >> 4;                                               \
            int c4  = idx & 15;                                               \
            float4 v = areg[l];                                               \
            float hx = __bfloat162float(__float2bfloat16(v.x));               \
            float hy = __bfloat162float(__float2bfloat16(v.y));               \
            float hz = __bfloat162float(__float2bfloat16(v.z));               \
            float hw = __bfloat162float(__float2bfloat16(v.w));               \
            uint32_t* ph = &As_hi[r * STRP + c4 * 2];                         \
            uint32_t* pl = &As_lo[r * STRP + c4 * 2];                         \
            ph[0] = pack_bf16x2(hx, hy);                                      \
            ph[1] = pack_bf16x2(hz, hw);                                      \
            pl[0] = pack_bf16x2(v.x - hx, v.y - hy);                          \
            pl[1] = pack_bf16x2(v.z - hz, v.w - hw);                          \
        }                                                                     \
    } while (0)

    #define CPASYNC_B(t_, buf_) do {                                          \
        const __nv_bfloat16* Bh_ = Bhb[(t_) >> 1] + ((t_) & 1) * BK;          \
        const __nv_bfloat16* Bl_ = Blb[(t_) >> 1] + ((t_) & 1) * BK;          \
        uint32_t hi_base = bs_b + (uint32_t)(buf_) * 2u * BBUF * 4u;          \
        uint32_t lo_base = hi_base + (uint32_t)BBUF * 4u;                     \
        _Pragma("unroll")                                                     \
        for (int l = 0; l < (BN * 8) / 256; l++) {                            \
            int idx = tid + l * 256;                                          \
            int n   = idx >> 3;                                               \
            int q   = idx & 7;                                                \
            uint32_t so = (uint32_t)(n * STRP + q * 4) * 4u;                  \
            cp16(hi_base + so, &Bh_[(size_t)n * DD + q * 8]);                 \
            cp16(lo_base + so, &Bl_[(size_t)n * DD + q * 8]);                 \
        }                                                                     \
        cp_commit();                                                          \
    } while (0)

    // ---- prologue: tile 0 ----
    LOAD_A_REG(0);
    CPASYNC_B(0, 0);
    STORE_A_SMEM();
    cp_wait0();
    __syncthreads();

    // ---- pipelined main loop over k-tiles ----
    #pragma unroll 1
    for (int t = 0; t < T; t++) {
        int buf = t & 1;
        bool has_next = (t + 1 < T);
        if (has_next) {
            LOAD_A_REG(t + 1);          // gmem latency hidden under MMAs
            CPASYNC_B(t + 1, buf ^ 1);
        }

        uint32_t bhi_base = bs_b + (uint32_t)buf * 2u * BBUF * 4u;
        uint32_t blo_base = bhi_base + (uint32_t)BBUF * 4u;

        #pragma unroll
        for (int ks = 0; ks < BK / 16; ks++) {
            int kp = ks * 8;
            uint32_t ah[2][4], al[2][4];
            #pragma unroll
            for (int mt = 0; mt < 2; mt++) {
                uint32_t off = ((uint32_t)(wm * 32 + mt * 16) * STRP
                                + (uint32_t)kp + a_row_off) * 4u;
                ldmx4(ah[mt], as_hi_b + off);
                ldmx4(al[mt], as_lo_b + off);
            }
            #pragma unroll
            for (int p = 0; p < NP; p++) {
                uint32_t off = ((uint32_t)(wn * WN + p * 16) * STRP
                                + (uint32_t)kp + b_row_off) * 4u;
                uint32_t bh[4], bl[4];
                ldmx4(bh, bhi_base + off);
                ldmx4(bl, blo_base + off);
                #pragma unroll
                for (int sub = 0; sub < 2; sub++) {
                    int nt = p * 2 + sub;
                    #pragma unroll
                    for (int mt = 0; mt < 2; mt++) {
                        mma16(c[mt][nt], ah[mt], bh[2*sub], bh[2*sub+1]);
                        mma16(c[mt][nt], ah[mt], bl[2*sub], bl[2*sub+1]);
                        mma16(c[mt][nt], al[mt], bh[2*sub], bh[2*sub+1]);
                    }
                }
            }
        }
        __syncthreads();                // everyone done reading As + Bs[buf]
        if (has_next) {
            STORE_A_SMEM();             // write next A tile
            cp_wait0();                 // next B landed
            __syncthreads();
        }
    }

    // ---- epilogue: bias + relu ----
    const int g = lane >> 2;
    #pragma unroll
    for (int mt = 0; mt < 2; mt++) {
        int row = brow + wm * 32 + mt * 16 + g;
        #pragma unroll
        for (int nt = 0; nt < NT; nt++) {
            int col = wn * WN + nt * 8 + 2 * t4;
            float b0 = bias[col], b1 = bias[col + 1];
            if (row < N) {
                float2 v;
                v.x = fmaxf(c[mt][nt][0] + b0, 0.0f);
                v.y = fmaxf(c[mt][nt][1] + b1, 0.0f);
                *reinterpret_cast<float2*>(&C[(size_t)row * M + col]) = v;
            }
            if (row + 8 < N) {
                float2 v;
                v.x = fmaxf(c[mt][nt][2] + b0, 0.0f);
                v.y = fmaxf(c[mt][nt][3] + b1, 0.0f);
                *reinterpret_cast<float2*>(&C[(size_t)(row + 8) * M + col]) = v;
            }
        }
    }
    #undef LOAD_A_REG
    #undef STORE_A_SMEM
    #undef CPASYNC_B
}

// ---------------------------------------------------------------------------
// log-softmax over 64 classes: one warp per row
// ---------------------------------------------------------------------------
__global__ void log_softmax_kernel(const float* __restrict__ h,
                                   float* __restrict__ out, int N)
{
    int row  = blockIdx.x * 8 + (threadIdx.x >> 5);
    int lane = threadIdx.x & 31;
    if (row >= N) return;
    const float* r = h + (size_t)row * NCLS;
    float v0 = r[lane];
    float v1 = r[lane + 32];
    float mx = fmaxf(v0, v1);
    #pragma unroll
    for (int o = 16; o; o >>= 1)
        mx = fmaxf(mx, __shfl_xor_sync(0xFFFFFFFFu, mx, o));
    float s = expf(v0 - mx) + expf(v1 - mx);
    #pragma unroll
    for (int o = 16; o; o >>= 1)
        s += __shfl_xor_sync(0xFFFFFFFFu, s, o);
    float lse = logf(s) + mx;
    out[(size_t)row * NCLS + lane]      = v0 - lse;
    out[(size_t)row * NCLS + lane + 32] = v1 - lse;
}

// ---------------------------------------------------------------------------
// Launch
// ---------------------------------------------------------------------------
extern "C" void kernel_launch(void* const* d_in, const int* in_sizes, int n_in,
                              void* d_out, int out_size)
{
    const float* x    = (const float*)d_in[0];
    const int*   esrc = (const int*)  d_in[1];
    const int*   edst = (const int*)  d_in[2];

    const float* Wp[3], *bp[3], *Ws[3], *Wn[3], *bn[3];
    for (int i = 0; i < 3; i++) {
        Wp[i] = (const float*)d_in[3 + 5 * i + 0];
        bp[i] = (const float*)d_in[3 + 5 * i + 1];
        Ws[i] = (const float*)d_in[3 + 5 * i + 2];
        Wn[i] = (const float*)d_in[3 + 5 * i + 3];
        bn[i] = (const float*)d_in[3 + 5 * i + 4];
    }

    float *m_p, *agg_p, *h1_p, *h2_p;
    cudaGetSymbolAddress((void**)&m_p,   g_m);
    cudaGetSymbolAddress((void**)&agg_p, g_agg);
    cudaGetSymbolAddress((void**)&h1_p,  g_h1);
    cudaGetSymbolAddress((void**)&h2_p,  g_h2);
    __nv_bfloat16 *wh_p, *wl_p;
    cudaGetSymbolAddress((void**)&wh_p, g_wh);
    cudaGetSymbolAddress((void**)&wl_p, g_wl);

    const int N = NN, E = EE;

    // smem: A 2*128*36 + B 2 bufs * 2(hi/lo) * BN*36, u32 units
    size_t smem128 = (size_t)(2 * 128 * 36 + 4 * 128 * 36) * 4;  // 110592
    size_t smem64  = (size_t)(2 * 128 * 36 + 4 *  64 * 36) * 4;  // 73728
    cudaFuncSetAttribute(sage_gemm_bf16<128>,
                         cudaFuncAttributeMaxDynamicSharedMemorySize, (int)smem128);
    cudaFuncSetAttribute(sage_gemm_bf16<64>,
                         cudaFuncAttributeMaxDynamicSharedMemorySize, (int)smem64);

    // ---- weight prep (launch 1) ----
    WPrep wp;
    const float* wsrc[9] = { Wp[0], Ws[0], Wn[0],
                             Wp[1], Ws[1], Wn[1],
                             Wp[2], Ws[2], Wn[2] };
    int wM[9] = { DD, DD, DD, DD, DD, DD, DD, NCLS, NCLS };
    for (int i = 0; i < 9; i++) { wp.src[i] = wsrc[i]; wp.M[i] = wM[i]; }
    prep_weights<<<dim3((DD * DD + 255) / 256, 9), 256>>>(wp, wh_p, wl_p);

    // ---- CSR build, part 1 (launches 2-5) ----
    const int SCAN_BLKS = (NN + 1023) / 1024;    // 98
    zero_deg_kernel<<<(NN + 255) / 256, 256>>>();
    count_kernel<<<(E + 255) / 256, 256>>>(edst);
    scan1_kernel<<<SCAN_BLKS, 256>>>();
    scan2_kernel<<<1, 1>>>(SCAN_BLKS);

    dim3 ggrid(1, (N + 127) / 128);
    const float* h = x;
    float* hbuf[2] = { h1_p, h2_p };

    // launch 6: layer-0 pool GEMM (profiled by ncu -s 5 -c 1)
    {
        const __nv_bfloat16* wph = wh_p + 0 * DD * DD;
        const __nv_bfloat16* wpl = wl_p + 0 * DD * DD;
        sage_gemm_bf16<128><<<ggrid, 256, smem128>>>(
            x, wph, wpl, nullptr, nullptr, nullptr, bp[0], m_p, N, DD);
    }

    // ---- CSR build, part 2 (independent of GEMM) ----
    scan3_kernel<<<SCAN_BLKS, 256>>>();
    fill_kernel<<<(E + 255) / 256, 256>>>(esrc, edst);

    for (int layer = 0; layer < 3; layer++) {
        const __nv_bfloat16* wph = wh_p + (layer * 3 + 0) * DD * DD;
        const __nv_bfloat16* wpl = wl_p + (layer * 3 + 0) * DD * DD;
        const __nv_bfloat16* wsh = wh_p + (layer * 3 + 1) * DD * DD;
        const __nv_bfloat16* wsl = wl_p + (layer * 3 + 1) * DD * DD;
        const __nv_bfloat16* wnh = wh_p + (layer * 3 + 2) * DD * DD;
        const __nv_bfloat16* wnl = wl_p + (layer * 3 + 2) * DD * DD;

        // 1) m = relu(h @ Wp + bp)  (layer 0 already issued above)
        if (layer > 0) {
            sage_gemm_bf16<128><<<ggrid, 256, smem128>>>(
                h, wph, wpl, nullptr, nullptr, nullptr, bp[layer], m_p, N, DD);
        }

        // 2) agg = segment_max(m[src], dst) via CSR gather-max
        aggregate_kernel<<<(N + 7) / 8, 256>>>(m_p, agg_p, N);

        // 3) h' = relu(h @ Ws + agg @ Wn + bn)
        if (layer < 2) {
            float* out = hbuf[layer & 1];
            sage_gemm_bf16<128><<<ggrid, 256, smem128>>>(
                h, wsh, wsl, agg_p, wnh, wnl, bn[layer], out, N, DD);
            h = out;
        } else {
            sage_gemm_bf16<64><<<ggrid, 256, smem64>>>(
                h, wsh, wsl, agg_p, wnh, wnl, bn[layer], m_p, N, NCLS);
        }
    }

    log_softmax_kernel<<<(N + 7) / 8, 256>>>(m_p, (float*)d_out, N);
}

// round 6
// speedup vs baseline: 3.9838x; 1.0197x over previous
#include <cuda_runtime.h>
#include <cuda_bf16.h>
#include <cstdint>
#include <cstddef>

#define NN 100000
#define EE 800000
#define DD 128
#define NCLS 64

// ---------------------------------------------------------------------------
// Scratch (no runtime allocation allowed)
// ---------------------------------------------------------------------------
__device__ float g_m  [(size_t)NN * DD];
__device__ float g_agg[(size_t)NN * DD];
__device__ float g_h1 [(size_t)NN * DD];
__device__ float g_h2 [(size_t)NN * DD];
__device__ __nv_bfloat16 g_wh[9][DD * DD];
__device__ __nv_bfloat16 g_wl[9][DD * DD];
__device__ int g_deg[NN];
__device__ int g_off[NN];
__device__ int g_cur[NN];
__device__ int g_csr[EE];
__device__ int g_part[128];

// ---------------------------------------------------------------------------
// Weight prep
// ---------------------------------------------------------------------------
struct WPrep { const float* src[9]; int M[9]; };

__global__ void prep_weights(WPrep p, __nv_bfloat16* __restrict__ hi,
                             __nv_bfloat16* __restrict__ lo)
{
    int w = blockIdx.y;
    int M = p.M[w];
    int idx = blockIdx.x * blockDim.x + threadIdx.x;
    if (idx >= DD * M) return;
    int k = idx / M;
    int m = idx % M;
    float v = p.src[w][idx];
    __nv_bfloat16 h = __float2bfloat16(v);
    float r = v - __bfloat162float(h);
    hi[(size_t)w * DD * DD + m * DD + k] = h;
    lo[(size_t)w * DD * DD + m * DD + k] = __float2bfloat16(r);
}

// ---------------------------------------------------------------------------
// CSR build
// ---------------------------------------------------------------------------
__global__ void zero_deg_kernel()
{
    int i = blockIdx.x * blockDim.x + threadIdx.x;
    if (i < NN) g_deg[i] = 0;
}

__global__ void count_kernel(const int* __restrict__ dst)
{
    int e = blockIdx.x * blockDim.x + threadIdx.x;
    if (e < EE) atomicAdd(&g_deg[dst[e]], 1);
}

__global__ void scan1_kernel()
{
    __shared__ int sh[256];
    int tid = threadIdx.x;
    int base = blockIdx.x * 1024 + tid * 4;
    int s = 0;
    #pragma unroll
    for (int j = 0; j < 4; j++) {
        int idx = base + j;
        if (idx < NN) s += g_deg[idx];
    }
    sh[tid] = s;
    __syncthreads();
    for (int o = 128; o; o >>= 1) {
        if (tid < o) sh[tid] += sh[tid + o];
        __syncthreads();
    }
    if (tid == 0) g_part[blockIdx.x] = sh[0];
}

__global__ void scan2_kernel(int nblk)
{
    int run = 0;
    for (int i = 0; i < nblk; i++) {
        int v = g_part[i];
        g_part[i] = run;
        run += v;
    }
}

__global__ void scan3_kernel()
{
    __shared__ int sh[256];
    int tid = threadIdx.x;
    int base = blockIdx.x * 1024 + tid * 4;
    int v[4];
    int s = 0;
    #pragma unroll
    for (int j = 0; j < 4; j++) {
        int idx = base + j;
        v[j] = (idx < NN) ? g_deg[idx] : 0;
        s += v[j];
    }
    sh[tid] = s;
    __syncthreads();
    #pragma unroll
    for (int o = 1; o < 256; o <<= 1) {
        int x = (tid >= o) ? sh[tid - o] : 0;
        __syncthreads();
        sh[tid] += x;
        __syncthreads();
    }
    int run = sh[tid] - s + g_part[blockIdx.x];
    #pragma unroll
    for (int j = 0; j < 4; j++) {
        int idx = base + j;
        if (idx < NN) { g_off[idx] = run; g_cur[idx] = run; }
        run += v[j];
    }
}

__global__ void fill_kernel(const int* __restrict__ src,
                            const int* __restrict__ dst)
{
    int e = blockIdx.x * blockDim.x + threadIdx.x;
    if (e < EE) {
        int p = atomicAdd(&g_cur[dst[e]], 1);
        g_csr[p] = src[e];
    }
}

// ---------------------------------------------------------------------------
// Aggregation: warp per node, gather-max (no atomics), MLP-8 unroll
// ---------------------------------------------------------------------------
__global__ void aggregate_kernel(const float* __restrict__ m,
                                 float* __restrict__ agg, int N)
{
    int node = blockIdx.x * 8 + (threadIdx.x >> 5);
    int lane = threadIdx.x & 31;
    if (node >= N) return;
    int o = g_off[node];
    int d = g_deg[node];
    float4 acc = make_float4(0.f, 0.f, 0.f, 0.f);
    int i = 0;
    for (; i + 8 <= d; i += 8) {
        int s[8];
        #pragma unroll
        for (int j = 0; j < 8; j++) s[j] = g_csr[o + i + j];
        float4 v[8];
        #pragma unroll
        for (int j = 0; j < 8; j++)
            v[j] = *reinterpret_cast<const float4*>(&m[(size_t)s[j] * DD + lane * 4]);
        #pragma unroll
        for (int j = 0; j < 8; j++) {
            acc.x = fmaxf(acc.x, v[j].x);
            acc.y = fmaxf(acc.y, v[j].y);
            acc.z = fmaxf(acc.z, v[j].z);
            acc.w = fmaxf(acc.w, v[j].w);
        }
    }
    for (; i + 4 <= d; i += 4) {
        int s[4];
        #pragma unroll
        for (int j = 0; j < 4; j++) s[j] = g_csr[o + i + j];
        float4 v[4];
        #pragma unroll
        for (int j = 0; j < 4; j++)
            v[j] = *reinterpret_cast<const float4*>(&m[(size_t)s[j] * DD + lane * 4]);
        #pragma unroll
        for (int j = 0; j < 4; j++) {
            acc.x = fmaxf(acc.x, v[j].x);
            acc.y = fmaxf(acc.y, v[j].y);
            acc.z = fmaxf(acc.z, v[j].z);
            acc.w = fmaxf(acc.w, v[j].w);
        }
    }
    for (; i < d; i++) {
        int s = g_csr[o + i];
        float4 v = *reinterpret_cast<const float4*>(&m[(size_t)s * DD + lane * 4]);
        acc.x = fmaxf(acc.x, v.x);
        acc.y = fmaxf(acc.y, v.y);
        acc.z = fmaxf(acc.z, v.z);
        acc.w = fmaxf(acc.w, v.w);
    }
    *reinterpret_cast<float4*>(&agg[(size_t)node * DD + lane * 4]) = acc;
}

// ---------------------------------------------------------------------------
// mma / ldmatrix / cp.async helpers
// ---------------------------------------------------------------------------
__device__ __forceinline__ void mma16(float* c, const uint32_t* a,
                                      uint32_t b0, uint32_t b1)
{
    asm volatile(
        "mma.sync.aligned.m16n8k16.row.col.f32.bf16.bf16.f32 "
        "{%0,%1,%2,%3}, {%4,%5,%6,%7}, {%8,%9}, {%0,%1,%2,%3};\n"
        : "+f"(c[0]), "+f"(c[1]), "+f"(c[2]), "+f"(c[3])
        : "r"(a[0]), "r"(a[1]), "r"(a[2]), "r"(a[3]),
          "r"(b0), "r"(b1));
}

__device__ __forceinline__ void ldmx4(uint32_t* r, uint32_t addr)
{
    asm volatile(
        "ldmatrix.sync.aligned.m8n8.x4.shared.b16 {%0,%1,%2,%3}, [%4];"
        : "=r"(r[0]), "=r"(r[1]), "=r"(r[2]), "=r"(r[3]) : "r"(addr));
}

__device__ __forceinline__ void cp16(uint32_t saddr, const void* gaddr)
{
    asm volatile("cp.async.cg.shared.global [%0], [%1], 16;\n"
                 :: "r"(saddr), "l"(gaddr));
}

__device__ __forceinline__ void cp_commit()
{
    asm volatile("cp.async.commit_group;\n");
}

__device__ __forceinline__ void cp_wait0()
{
    asm volatile("cp.async.wait_group 0;\n");
}

__device__ __forceinline__ uint32_t pack_bf16x2(float a, float b)
{
    __nv_bfloat162 h = __floats2bfloat162_rn(a, b);
    return *reinterpret_cast<uint32_t*>(&h);
}

// ---------------------------------------------------------------------------
// Dual-source bf16-split tensor-core GEMM, software-pipelined.
//   C = relu(A1 @ W1 [+ A2 @ W2] + bias), K = 128 fixed.
// FUSE_LSM: instead of storing C, compute log-softmax over the M=64 row
// (values staged in smem) and write log-probs to C.
// ---------------------------------------------------------------------------
template<int BN, bool FUSE_LSM>
__global__ void __launch_bounds__(256, 2)
sage_gemm_bf16(const float* __restrict__ A1,
               const __nv_bfloat16* __restrict__ B1h,
               const __nv_bfloat16* __restrict__ B1l,
               const float* __restrict__ A2,
               const __nv_bfloat16* __restrict__ B2h,
               const __nv_bfloat16* __restrict__ B2l,
               const float* __restrict__ bias, float* __restrict__ C,
               int N, int M)
{
    constexpr int BM   = 128;
    constexpr int BK   = 64;
    constexpr int STRP = 36;          // u32 per row (32 data + 4 pad)
    constexpr int WN   = BN / 2;
    constexpr int NT   = BN / 16;
    constexpr int NP   = NT / 2;
    constexpr int BBUF = BN * STRP;

    extern __shared__ __align__(16) uint32_t smem_u[];
    uint32_t* As_hi = smem_u;
    uint32_t* As_lo = As_hi + BM * STRP;
    uint32_t* Bs    = As_lo + BM * STRP;

    const int tid  = threadIdx.x;
    const int lane = tid & 31;
    const int warp = tid >> 5;
    const int wm   = warp & 3;
    const int wn   = warp >> 2;
    const int t4   = lane & 3;
    const int brow = blockIdx.y * BM;

    const uint32_t as_hi_b = (uint32_t)__cvta_generic_to_shared(As_hi);
    const uint32_t as_lo_b = (uint32_t)__cvta_generic_to_shared(As_lo);
    const uint32_t bs_b    = (uint32_t)__cvta_generic_to_shared(Bs);

    const uint32_t a_row_off = (uint32_t)(lane & 15) * STRP + (uint32_t)(lane >> 4) * 4;
    const uint32_t b_row_off = ((uint32_t)(lane & 7) + (uint32_t)(lane >> 4) * 8) * STRP
                             + (uint32_t)((lane >> 3) & 1) * 4;

    const float* Ab[2]            = { A1, A2 ? A2 : A1 };
    const __nv_bfloat16* Bhb[2]   = { B1h, B2h ? B2h : B1h };
    const __nv_bfloat16* Blb[2]   = { B1l, B2l ? B2l : B1l };
    const int T = A2 ? 4 : 2;

    float c[2][NT][4];
    #pragma unroll
    for (int mt = 0; mt < 2; mt++)
        #pragma unroll
        for (int nt = 0; nt < NT; nt++)
            #pragma unroll
            for (int i = 0; i < 4; i++) c[mt][nt][i] = 0.0f;

    float4 areg[8];

    #define LOAD_A_REG(t_) do {                                               \
        const float* A_ = Ab[(t_) >> 1];                                      \
        int koff_ = ((t_) & 1) * BK;                                          \
        _Pragma("unroll")                                                     \
        for (int l = 0; l < 8; l++) {                                         \
            int idx = tid + l * 256;                                          \
            int r   = idx >> 4;                                               \
            int c4  = idx & 15;                                               \
            int grow = brow + r;                                              \
            areg[l] = (grow < N)                                              \
                ? *reinterpret_cast<const float4*>(                           \
                      &A_[(size_t)grow * DD + koff_ + c4 * 4])                \
                : make_float4(0.f, 0.f, 0.f, 0.f);                            \
        }                                                                     \
    } while (0)

    #define STORE_A_SMEM() do {                                               \
        _Pragma("unroll")                                                     \
        for (int l = 0; l < 8; l++) {                                         \
            int idx = tid + l * 256;                                          \
            int r   = idx >> 4;                                               \
            int c4  = idx & 15;                                               \
            float4 v = areg[l];                                               \
            float hx = __bfloat162float(__float2bfloat16(v.x));               \
            float hy = __bfloat162float(__float2bfloat16(v.y));               \
            float hz = __bfloat162float(__float2bfloat16(v.z));               \
            float hw = __bfloat162float(__float2bfloat16(v.w));               \
            uint32_t* ph = &As_hi[r * STRP + c4 * 2];                         \
            uint32_t* pl = &As_lo[r * STRP + c4 * 2];                         \
            ph[0] = pack_bf16x2(hx, hy);                                      \
            ph[1] = pack_bf16x2(hz, hw);                                      \
            pl[0] = pack_bf16x2(v.x - hx, v.y - hy);                          \
            pl[1] = pack_bf16x2(v.z - hz, v.w - hw);                          \
        }                                                                     \
    } while (0)

    #define CPASYNC_B(t_, buf_) do {                                          \
        const __nv_bfloat16* Bh_ = Bhb[(t_) >> 1] + ((t_) & 1) * BK;          \
        const __nv_bfloat16* Bl_ = Blb[(t_) >> 1] + ((t_) & 1) * BK;          \
        uint32_t hi_base = bs_b + (uint32_t)(buf_) * 2u * BBUF * 4u;          \
        uint32_t lo_base = hi_base + (uint32_t)BBUF * 4u;                     \
        _Pragma("unroll")                                                     \
        for (int l = 0; l < (BN * 8) / 256; l++) {                            \
            int idx = tid + l * 256;                                          \
            int n   = idx >> 3;                                               \
            int q   = idx & 7;                                                \
            uint32_t so = (uint32_t)(n * STRP + q * 4) * 4u;                  \
            cp16(hi_base + so, &Bh_[(size_t)n * DD + q * 8]);                 \
            cp16(lo_base + so, &Bl_[(size_t)n * DD + q * 8]);                 \
        }                                                                     \
        cp_commit();                                                          \
    } while (0)

    // ---- prologue ----
    LOAD_A_REG(0);
    CPASYNC_B(0, 0);
    STORE_A_SMEM();
    cp_wait0();
    __syncthreads();

    // ---- pipelined main loop ----
    #pragma unroll 1
    for (int t = 0; t < T; t++) {
        int buf = t & 1;
        bool has_next = (t + 1 < T);
        if (has_next) {
            LOAD_A_REG(t + 1);
            CPASYNC_B(t + 1, buf ^ 1);
        }

        uint32_t bhi_base = bs_b + (uint32_t)buf * 2u * BBUF * 4u;
        uint32_t blo_base = bhi_base + (uint32_t)BBUF * 4u;

        #pragma unroll
        for (int ks = 0; ks < BK / 16; ks++) {
            int kp = ks * 8;
            uint32_t ah[2][4], al[2][4];
            #pragma unroll
            for (int mt = 0; mt < 2; mt++) {
                uint32_t off = ((uint32_t)(wm * 32 + mt * 16) * STRP
                                + (uint32_t)kp + a_row_off) * 4u;
                ldmx4(ah[mt], as_hi_b + off);
                ldmx4(al[mt], as_lo_b + off);
            }
            #pragma unroll
            for (int p = 0; p < NP; p++) {
                uint32_t off = ((uint32_t)(wn * WN + p * 16) * STRP
                                + (uint32_t)kp + b_row_off) * 4u;
                uint32_t bh[4], bl[4];
                ldmx4(bh, bhi_base + off);
                ldmx4(bl, blo_base + off);
                #pragma unroll
                for (int sub = 0; sub < 2; sub++) {
                    int nt = p * 2 + sub;
                    #pragma unroll
                    for (int mt = 0; mt < 2; mt++) {
                        mma16(c[mt][nt], ah[mt], bh[2*sub], bh[2*sub+1]);
                        mma16(c[mt][nt], ah[mt], bl[2*sub], bl[2*sub+1]);
                        mma16(c[mt][nt], al[mt], bh[2*sub], bh[2*sub+1]);
                    }
                }
            }
        }
        __syncthreads();
        if (has_next) {
            STORE_A_SMEM();
            cp_wait0();
            __syncthreads();
        }
    }

    const int g = lane >> 2;

    if (!FUSE_LSM) {
        // ---- epilogue: bias + relu -> gmem ----
        #pragma unroll
        for (int mt = 0; mt < 2; mt++) {
            int row = brow + wm * 32 + mt * 16 + g;
            #pragma unroll
            for (int nt = 0; nt < NT; nt++) {
                int col = wn * WN + nt * 8 + 2 * t4;
                float b0 = bias[col], b1 = bias[col + 1];
                if (row < N) {
                    float2 v;
                    v.x = fmaxf(c[mt][nt][0] + b0, 0.0f);
                    v.y = fmaxf(c[mt][nt][1] + b1, 0.0f);
                    *reinterpret_cast<float2*>(&C[(size_t)row * M + col]) = v;
                }
                if (row + 8 < N) {
                    float2 v;
                    v.x = fmaxf(c[mt][nt][2] + b0, 0.0f);
                    v.y = fmaxf(c[mt][nt][3] + b1, 0.0f);
                    *reinterpret_cast<float2*>(&C[(size_t)(row + 8) * M + col]) = v;
                }
            }
        }
    } else {
        // ---- epilogue: bias + relu -> smem, then row log-softmax -> gmem ----
        constexpr int SSTR = 68;               // f32 stride per row
        float* sf = reinterpret_cast<float*>(smem_u);   // 128 x 68 = 34816 B
        #pragma unroll
        for (int mt = 0; mt < 2; mt++) {
            int rl = wm * 32 + mt * 16 + g;
            #pragma unroll
            for (int nt = 0; nt < NT; nt++) {
                int col = wn * WN + nt * 8 + 2 * t4;
                float b0 = bias[col], b1 = bias[col + 1];
                float2 v0, v1;
                v0.x = fmaxf(c[mt][nt][0] + b0, 0.0f);
                v0.y = fmaxf(c[mt][nt][1] + b1, 0.0f);
                v1.x = fmaxf(c[mt][nt][2] + b0, 0.0f);
                v1.y = fmaxf(c[mt][nt][3] + b1, 0.0f);
                *reinterpret_cast<float2*>(&sf[rl * SSTR + col])       = v0;
                *reinterpret_cast<float2*>(&sf[(rl + 8) * SSTR + col]) = v1;
            }
        }
        __syncthreads();
        #pragma unroll 1
        for (int r = warp; r < BM; r += 8) {
            int grow = brow + r;
            if (grow >= N) continue;           // warp-uniform
            float v0 = sf[r * SSTR + lane];
            float v1 = sf[r * SSTR + lane + 32];
            float mx = fmaxf(v0, v1);
            #pragma unroll
            for (int o = 16; o; o >>= 1)
                mx = fmaxf(mx, __shfl_xor_sync(0xFFFFFFFFu, mx, o));
            float s = expf(v0 - mx) + expf(v1 - mx);
            #pragma unroll
            for (int o = 16; o; o >>= 1)
                s += __shfl_xor_sync(0xFFFFFFFFu, s, o);
            float lse = logf(s) + mx;
            C[(size_t)grow * NCLS + lane]      = v0 - lse;
            C[(size_t)grow * NCLS + lane + 32] = v1 - lse;
        }
    }
    #undef LOAD_A_REG
    #undef STORE_A_SMEM
    #undef CPASYNC_B
}

// ---------------------------------------------------------------------------
// Launch
// ---------------------------------------------------------------------------
extern "C" void kernel_launch(void* const* d_in, const int* in_sizes, int n_in,
                              void* d_out, int out_size)
{
    const float* x    = (const float*)d_in[0];
    const int*   esrc = (const int*)  d_in[1];
    const int*   edst = (const int*)  d_in[2];

    const float* Wp[3], *bp[3], *Ws[3], *Wn[3], *bn[3];
    for (int i = 0; i < 3; i++) {
        Wp[i] = (const float*)d_in[3 + 5 * i + 0];
        bp[i] = (const float*)d_in[3 + 5 * i + 1];
        Ws[i] = (const float*)d_in[3 + 5 * i + 2];
        Wn[i] = (const float*)d_in[3 + 5 * i + 3];
        bn[i] = (const float*)d_in[3 + 5 * i + 4];
    }

    float *m_p, *agg_p, *h1_p, *h2_p;
    cudaGetSymbolAddress((void**)&m_p,   g_m);
    cudaGetSymbolAddress((void**)&agg_p, g_agg);
    cudaGetSymbolAddress((void**)&h1_p,  g_h1);
    cudaGetSymbolAddress((void**)&h2_p,  g_h2);
    __nv_bfloat16 *wh_p, *wl_p;
    cudaGetSymbolAddress((void**)&wh_p, g_wh);
    cudaGetSymbolAddress((void**)&wl_p, g_wl);

    const int N = NN, E = EE;

    size_t smem128 = (size_t)(2 * 128 * 36 + 4 * 128 * 36) * 4;  // 110592
    size_t smem64  = (size_t)(2 * 128 * 36 + 4 *  64 * 36) * 4;  // 73728
    cudaFuncSetAttribute(sage_gemm_bf16<128, false>,
                         cudaFuncAttributeMaxDynamicSharedMemorySize, (int)smem128);
    cudaFuncSetAttribute(sage_gemm_bf16<64, true>,
                         cudaFuncAttributeMaxDynamicSharedMemorySize, (int)smem64);

    // ---- weight prep ----
    WPrep wp;
    const float* wsrc[9] = { Wp[0], Ws[0], Wn[0],
                             Wp[1], Ws[1], Wn[1],
                             Wp[2], Ws[2], Wn[2] };
    int wM[9] = { DD, DD, DD, DD, DD, DD, DD, NCLS, NCLS };
    for (int i = 0; i < 9; i++) { wp.src[i] = wsrc[i]; wp.M[i] = wM[i]; }
    prep_weights<<<dim3((DD * DD + 255) / 256, 9), 256>>>(wp, wh_p, wl_p);

    // ---- CSR build, part 1 ----
    const int SCAN_BLKS = (NN + 1023) / 1024;    // 98
    zero_deg_kernel<<<(NN + 255) / 256, 256>>>();
    count_kernel<<<(E + 255) / 256, 256>>>(edst);
    scan1_kernel<<<SCAN_BLKS, 256>>>();
    scan2_kernel<<<1, 1>>>(SCAN_BLKS);

    dim3 ggrid(1, (N + 127) / 128);
    const float* h = x;
    float* hbuf[2] = { h1_p, h2_p };

    // layer-0 pool GEMM (independent of CSR part 2)
    {
        const __nv_bfloat16* wph = wh_p + 0 * DD * DD;
        const __nv_bfloat16* wpl = wl_p + 0 * DD * DD;
        sage_gemm_bf16<128, false><<<ggrid, 256, smem128>>>(
            x, wph, wpl, nullptr, nullptr, nullptr, bp[0], m_p, N, DD);
    }

    // ---- CSR build, part 2 ----
    scan3_kernel<<<SCAN_BLKS, 256>>>();
    fill_kernel<<<(E + 255) / 256, 256>>>(esrc, edst);

    for (int layer = 0; layer < 3; layer++) {
        const __nv_bfloat16* wph = wh_p + (layer * 3 + 0) * DD * DD;
        const __nv_bfloat16* wpl = wl_p + (layer * 3 + 0) * DD * DD;
        const __nv_bfloat16* wsh = wh_p + (layer * 3 + 1) * DD * DD;
        const __nv_bfloat16* wsl = wl_p + (layer * 3 + 1) * DD * DD;
        const __nv_bfloat16* wnh = wh_p + (layer * 3 + 2) * DD * DD;
        const __nv_bfloat16* wnl = wl_p + (layer * 3 + 2) * DD * DD;

        // 1) m = relu(h @ Wp + bp)  (layer 0 already issued above)
        if (layer > 0) {
            sage_gemm_bf16<128, false><<<ggrid, 256, smem128>>>(
                h, wph, wpl, nullptr, nullptr, nullptr, bp[layer], m_p, N, DD);
        }

        // 2) agg = segment_max(m[src], dst) via CSR gather-max
        aggregate_kernel<<<(N + 7) / 8, 256>>>(m_p, agg_p, N);

        // 3) h' = relu(h @ Ws + agg @ Wn + bn)  (final layer fuses log-softmax)
        if (layer < 2) {
            float* out = hbuf[layer & 1];
            sage_gemm_bf16<128, false><<<ggrid, 256, smem128>>>(
                h, wsh, wsl, agg_p, wnh, wnl, bn[layer], out, N, DD);
            h = out;
        } else {
            sage_gemm_bf16<64, true><<<ggrid, 256, smem64>>>(
                h, wsh, wsl, agg_p, wnh, wnl, bn[layer],
                (float*)d_out, N, NCLS);
        }
    }
}